// round 5
// baseline (speedup 1.0000x reference)
#include <cuda_runtime.h>
#include <cuda_bf16.h>
#include <math.h>
#include <stdint.h>

// ---------------------------------------------------------------------------
// Problem constants
// ---------------------------------------------------------------------------
#define B_   4
#define T_   2048
#define D_   1024
#define H_   16
#define G_   4
#define HD_  64
#define BT_  (B_ * T_)          // 8192
#define KVW  512                 // fused K|V projection width

// ---------------------------------------------------------------------------
// Scratch (device globals -- no allocation allowed)
// ---------------------------------------------------------------------------
__device__ float g_q[BT_ * D_];            // q projection fp32
__device__ float g_kv[BT_ * KVW];          // fused k|v projection fp32
__device__ float2 g_cs[T_ * 32];           // rope cos/sin table

__device__ __nv_bfloat16 g_xhi[BT_ * D_],  g_xlo[BT_ * D_];
__device__ __nv_bfloat16 g_wqhi[D_ * D_],  g_wqlo[D_ * D_];
__device__ __nv_bfloat16 g_wkvhi[KVW * D_], g_wkvlo[KVW * D_];
__device__ __nv_bfloat16 g_wohi[D_ * D_],  g_wolo[D_ * D_];
__device__ __nv_bfloat16 g_qhi[BT_ * D_],  g_qlo[BT_ * D_];
__device__ __nv_bfloat16 g_khi[BT_ * G_ * HD_], g_klo[BT_ * G_ * HD_];
__device__ __nv_bfloat16 g_vthi[B_ * G_ * HD_ * T_], g_vtlo[B_ * G_ * HD_ * T_];
__device__ __nv_bfloat16 g_ohi[BT_ * D_],  g_olo[BT_ * D_];

// ---------------------------------------------------------------------------
// PTX helpers (base sm_100-legal)
// ---------------------------------------------------------------------------
__device__ __forceinline__ uint32_t smem_u32(const void* p) {
    uint32_t a;
    asm("{ .reg .u64 t; cvta.to.shared.u64 t, %1; cvt.u32.u64 %0, t; }"
        : "=r"(a) : "l"(p));
    return a;
}
__device__ __forceinline__ void ldsm_x4(uint32_t (&r)[4], uint32_t addr) {
    asm volatile("ldmatrix.sync.aligned.m8n8.x4.shared.b16 {%0,%1,%2,%3}, [%4];"
                 : "=r"(r[0]), "=r"(r[1]), "=r"(r[2]), "=r"(r[3]) : "r"(addr));
}
__device__ __forceinline__ void ldsm_x2(uint32_t (&r)[2], uint32_t addr) {
    asm volatile("ldmatrix.sync.aligned.m8n8.x2.shared.b16 {%0,%1}, [%2];"
                 : "=r"(r[0]), "=r"(r[1]) : "r"(addr));
}
__device__ __forceinline__ void mma_bf16(float (&d)[4], const uint32_t (&a)[4],
                                         const uint32_t (&b)[2]) {
    asm volatile(
        "mma.sync.aligned.m16n8k16.row.col.f32.bf16.bf16.f32 "
        "{%0,%1,%2,%3}, {%4,%5,%6,%7}, {%8,%9}, {%0,%1,%2,%3};"
        : "+f"(d[0]), "+f"(d[1]), "+f"(d[2]), "+f"(d[3])
        : "r"(a[0]), "r"(a[1]), "r"(a[2]), "r"(a[3]), "r"(b[0]), "r"(b[1]));
}
__device__ __forceinline__ float ex2(float x) {
    float y;
    asm("ex2.approx.ftz.f32 %0, %1;" : "=f"(y) : "f"(x));
    return y;
}
__device__ __forceinline__ void packhl(float x, float y, uint32_t& hi, uint32_t& lo) {
    __nv_bfloat162 h = __floats2bfloat162_rn(x, y);
    float lx = x - __bfloat162float(h.x);
    float ly = y - __bfloat162float(h.y);
    __nv_bfloat162 l2 = __floats2bfloat162_rn(lx, ly);
    hi = *(uint32_t*)&h; lo = *(uint32_t*)&l2;
}
#define STS128(addr, v) \
    asm volatile("st.shared.v4.b32 [%0], {%1,%2,%3,%4};" \
                 :: "r"(addr), "r"((v).x), "r"((v).y), "r"((v).z), "r"((v).w))
#define CP_ASYNC16(dst, src) \
    asm volatile("cp.async.cg.shared.global [%0], [%1], 16;" \
                 :: "r"(dst), "l"(src))
#define CP_COMMIT() asm volatile("cp.async.commit_group;" ::: "memory")
#define CP_WAIT1()  asm volatile("cp.async.wait_group 1;" ::: "memory")
#define CP_WAIT0()  asm volatile("cp.async.wait_group 0;" ::: "memory")

// ---------------------------------------------------------------------------
// fp32 -> bf16 hi/lo converter (float4 granularity)
// ---------------------------------------------------------------------------
__global__ void __launch_bounds__(256)
f2bf(const float* __restrict__ in, __nv_bfloat16* __restrict__ hi,
     __nv_bfloat16* __restrict__ lo, int n4)
{
    const int i = blockIdx.x * 256 + threadIdx.x;
    if (i >= n4) return;
    float4 v = ((const float4*)in)[i];
    __nv_bfloat162 ha = __floats2bfloat162_rn(v.x, v.y);
    __nv_bfloat162 hb = __floats2bfloat162_rn(v.z, v.w);
    __nv_bfloat162 la = __floats2bfloat162_rn(v.x - __bfloat162float(ha.x),
                                              v.y - __bfloat162float(ha.y));
    __nv_bfloat162 lb = __floats2bfloat162_rn(v.z - __bfloat162float(hb.x),
                                              v.w - __bfloat162float(hb.y));
    uint2 ho = {*(uint32_t*)&ha, *(uint32_t*)&hb};
    uint2 lov = {*(uint32_t*)&la, *(uint32_t*)&lb};
    ((uint2*)hi)[i] = ho;
    ((uint2*)lo)[i] = lov;
}

// ---------------------------------------------------------------------------
// RoPE cos/sin table (fp64 once; 65536 entries)
// ---------------------------------------------------------------------------
__global__ void rope_table(float2* __restrict__ cs)
{
    const int t = blockIdx.x;
    const int l = threadIdx.x;
    double inv_freq = pow(10000.0, -(double)l / 32.0);
    double ang = (double)t * inv_freq;
    cs[t * 32 + l] = make_float2((float)cos(ang), (float)sin(ang));
}

// ---------------------------------------------------------------------------
// Tensor-core GEMM (HMMA, bf16x3) with pre-converted operands + cp.async.
// C[M,N] = A[M,K] @ B[N,K]^T. CTA 128x128, KC=32, 3-stage pipeline.
// ---------------------------------------------------------------------------
#define KC     32
#define LDT    40                        // padded smem stride (bf16)
#define TILEB  (128 * LDT * 2)           // 10240 B
#define STAGEB (4 * TILEB)               // 40960 B
#define GEMM_SMEM (3 * STAGEB)           // 122880 B

__global__ void __launch_bounds__(256, 1)
gemm_bf(const __nv_bfloat16* __restrict__ Ahi, const __nv_bfloat16* __restrict__ Alo,
        const __nv_bfloat16* __restrict__ Bhi, const __nv_bfloat16* __restrict__ Blo,
        float* __restrict__ C, int M, int N, int K)
{
    extern __shared__ char smraw[];
    const uint32_t sb = smem_u32(smraw);

    const int tid  = threadIdx.x;
    const int lane = tid & 31;
    const int wid  = tid >> 5;
    const int wm   = wid & 1;
    const int wn   = wid >> 1;
    const int m0 = blockIdx.y * 128;
    const int n0 = blockIdx.x * 128;

    // cp.async mapping: thread -> (row 0..63 [+64], 8-elem segment 0..3)
    const int r0   = tid >> 2;
    const int cseg = (tid & 3) * 8;
    const __nv_bfloat16* s0 = Ahi + (size_t)(m0 + r0) * K + cseg;
    const __nv_bfloat16* s1 = Alo + (size_t)(m0 + r0) * K + cseg;
    const __nv_bfloat16* s2 = Bhi + (size_t)(n0 + r0) * K + cseg;
    const __nv_bfloat16* s3 = Blo + (size_t)(n0 + r0) * K + cseg;
    const uint32_t dbase = (uint32_t)(r0 * LDT + cseg) * 2;
    const size_t rstep = (size_t)64 * K;
    const uint32_t dstep = 64 * LDT * 2;

    const uint32_t a_off = (uint32_t)(((wm * 64 + (lane & 15)) * LDT
                                       + (lane >> 4) * 8) * 2);
    const uint32_t b_off = (uint32_t)(((wn * 32 + (lane & 7)) * LDT
                                       + ((lane >> 3) & 1) * 8) * 2);

    float acc[4][4][4];
#pragma unroll
    for (int i = 0; i < 4; i++)
#pragma unroll
        for (int j = 0; j < 4; j++)
#pragma unroll
            for (int e = 0; e < 4; e++) acc[i][j][e] = 0.f;

    const int nch = K / KC;

    // issue chunk c into stage c%3
#define ISSUE(c) do {                                                   \
        const uint32_t st_ = sb + ((c) % 3) * STAGEB;                   \
        const size_t k0_ = (size_t)(c) * KC;                            \
        CP_ASYNC16(st_ + dbase,                     s0 + k0_);          \
        CP_ASYNC16(st_ + dbase + dstep,             s0 + k0_ + rstep);  \
        CP_ASYNC16(st_ + TILEB + dbase,             s1 + k0_);          \
        CP_ASYNC16(st_ + TILEB + dbase + dstep,     s1 + k0_ + rstep);  \
        CP_ASYNC16(st_ + 2 * TILEB + dbase,         s2 + k0_);          \
        CP_ASYNC16(st_ + 2 * TILEB + dbase + dstep, s2 + k0_ + rstep);  \
        CP_ASYNC16(st_ + 3 * TILEB + dbase,         s3 + k0_);          \
        CP_ASYNC16(st_ + 3 * TILEB + dbase + dstep, s3 + k0_ + rstep);  \
        CP_COMMIT();                                                    \
    } while (0)

    ISSUE(0);
    ISSUE(1);

    for (int c = 0; c < nch; c++) {
        if (c + 2 < nch) CP_WAIT1(); else CP_WAIT0();
        __syncthreads();
        if (c + 2 < nch) ISSUE(c + 2);

        const uint32_t tb = sb + (c % 3) * STAGEB;
        const uint32_t aHi = tb;
        const uint32_t aLo = tb + TILEB;
        const uint32_t bHi = tb + 2 * TILEB;
        const uint32_t bLo = tb + 3 * TILEB;

#pragma unroll
        for (int ks = 0; ks < 2; ks++) {
            const uint32_t ksb = ks * 32;
            uint32_t ahi[4][4], alo[4][4], bhi[4][2], blo[4][2];
#pragma unroll
            for (int mt = 0; mt < 4; mt++) {
                ldsm_x4(ahi[mt], aHi + a_off + mt * (16 * LDT * 2) + ksb);
                ldsm_x4(alo[mt], aLo + a_off + mt * (16 * LDT * 2) + ksb);
            }
#pragma unroll
            for (int nt = 0; nt < 4; nt++) {
                ldsm_x2(bhi[nt], bHi + b_off + nt * (8 * LDT * 2) + ksb);
                ldsm_x2(blo[nt], bLo + b_off + nt * (8 * LDT * 2) + ksb);
            }
#pragma unroll
            for (int mt = 0; mt < 4; mt++)
#pragma unroll
                for (int nt = 0; nt < 4; nt++) {
                    mma_bf16(acc[mt][nt], ahi[mt], bhi[nt]);
                    mma_bf16(acc[mt][nt], ahi[mt], blo[nt]);
                    mma_bf16(acc[mt][nt], alo[mt], bhi[nt]);
                }
        }
        __syncthreads();
    }
#undef ISSUE

#pragma unroll
    for (int mt = 0; mt < 4; mt++) {
        const int r = m0 + wm * 64 + mt * 16 + (lane >> 2);
#pragma unroll
        for (int nt = 0; nt < 4; nt++) {
            const int cc = n0 + wn * 32 + nt * 8 + (lane & 3) * 2;
            float2 v0 = {acc[mt][nt][0], acc[mt][nt][1]};
            float2 v1 = {acc[mt][nt][2], acc[mt][nt][3]};
            *(float2*)&C[(size_t)r * N + cc]       = v0;
            *(float2*)&C[(size_t)(r + 8) * N + cc] = v1;
        }
    }
}

// ---------------------------------------------------------------------------
// RMSNorm + RoPE (table-based), fp32 in (strided) -> bf16 hi/lo out (packed)
// ---------------------------------------------------------------------------
__global__ void __launch_bounds__(256)
rmsrope_bf16(const float* __restrict__ in, int rowstride,
             const float* __restrict__ w, int nheads,
             __nv_bfloat16* __restrict__ ohi, __nv_bfloat16* __restrict__ olo,
             const float2* __restrict__ cs)
{
    const int lane   = threadIdx.x & 31;
    const int warpid = threadIdx.x >> 5;
    const int row    = blockIdx.x * 8 + warpid;
    const int bt     = row / nheads;
    const int head   = row - bt * nheads;
    const int t      = bt & (T_ - 1);

    const float* p = in + (size_t)bt * rowstride + head * HD_;
    float2 x = *(const float2*)&p[2 * lane];

    float ss = x.x * x.x + x.y * x.y;
#pragma unroll
    for (int o = 16; o > 0; o >>= 1)
        ss += __shfl_xor_sync(0xffffffffu, ss, o);

    float rms = rsqrtf(ss * (1.0f / HD_) + 1e-6f);
    float xn1 = x.x * rms * w[2 * lane];
    float xn2 = x.y * rms * w[2 * lane + 1];

    float2 csv = cs[t * 32 + lane];
    float ox = xn1 * csv.x - xn2 * csv.y;
    float oy = xn2 * csv.x + xn1 * csv.y;

    const size_t idx = (size_t)bt * (nheads * HD_) + head * HD_ + 2 * lane;
    uint32_t hi, lo;
    packhl(ox, oy, hi, lo);
    *(uint32_t*)&ohi[idx] = hi;
    *(uint32_t*)&olo[idx] = lo;
}

// ---------------------------------------------------------------------------
// V convert + transpose: fp32 strided [bt, g*64] -> bf16 hi/lo [b,g,hd,T]
// ---------------------------------------------------------------------------
__global__ void __launch_bounds__(256)
vconv(const float* __restrict__ v, int rowstride,
      __nv_bfloat16* __restrict__ vth, __nv_bfloat16* __restrict__ vtl)
{
    __shared__ float s[64][65];
    const int t0 = blockIdx.x * 64;
    const int g  = blockIdx.y;
    const int b  = blockIdx.z;
    const int tid = threadIdx.x;

#pragma unroll
    for (int it = 0; it < 4; it++) {
        int tr = it * 16 + (tid >> 4);
        int c4 = (tid & 15) * 4;
        float4 val = *(const float4*)&v[(size_t)(b * T_ + t0 + tr) * rowstride
                                        + g * HD_ + c4];
        s[tr][c4 + 0] = val.x; s[tr][c4 + 1] = val.y;
        s[tr][c4 + 2] = val.z; s[tr][c4 + 3] = val.w;
    }
    __syncthreads();

    const int hd  = tid >> 2;
    const int seg = tid & 3;
    __nv_bfloat16 hi[16], lo[16];
#pragma unroll
    for (int j = 0; j < 16; j++) {
        float x = s[seg * 16 + j][hd];
        __nv_bfloat16 h = __float2bfloat16(x);
        hi[j] = h;
        lo[j] = __float2bfloat16(x - __bfloat162float(h));
    }
    const size_t ob = ((size_t)(b * G_ + g) * HD_ + hd) * T_ + t0 + seg * 16;
    *(uint4*)&vth[ob]     = *(uint4*)&hi[0];
    *(uint4*)&vth[ob + 8] = *(uint4*)&hi[8];
    *(uint4*)&vtl[ob]     = *(uint4*)&lo[0];
    *(uint4*)&vtl[ob + 8] = *(uint4*)&lo[8];
}

// ---------------------------------------------------------------------------
// Causal GQA flash attention, HMMA bf16x3; epilogue emits bf16 hi/lo.
// ---------------------------------------------------------------------------
#define ASTR  72
#define ATILE (64 * ASTR * 2)
#define AQT   (128 * ASTR * 2)
#define ATT_SMEM (2 * AQT + 4 * ATILE)
#define SC_LOG2E 0.18033688011112042f

__global__ void __launch_bounds__(256)
attn_mma(const __nv_bfloat16* __restrict__ qhi, const __nv_bfloat16* __restrict__ qlo,
         const __nv_bfloat16* __restrict__ khi, const __nv_bfloat16* __restrict__ klo,
         const __nv_bfloat16* __restrict__ vth, const __nv_bfloat16* __restrict__ vtl,
         __nv_bfloat16* __restrict__ obhi, __nv_bfloat16* __restrict__ oblo)
{
    extern __shared__ char smraw[];
    const uint32_t sb   = smem_u32(smraw);
    const uint32_t sQhi = sb;
    const uint32_t sQlo = sb + AQT;
    const uint32_t sKhi = sb + 2 * AQT;
    const uint32_t sKlo = sKhi + ATILE;
    const uint32_t sVhi = sKlo + ATILE;
    const uint32_t sVlo = sVhi + ATILE;

    const int tid  = threadIdx.x;
    const int lane = tid & 31;
    const int w    = tid >> 5;
    const int mblk = gridDim.x - 1 - blockIdx.x;
    const int m0   = mblk * 128;
    const int h    = blockIdx.y;
    const int b    = blockIdx.z;
    const int g    = h >> 2;

    {
        const __nv_bfloat16* qh = qhi + ((size_t)(b * T_ + m0) * H_ + h) * HD_;
        const __nv_bfloat16* ql = qlo + ((size_t)(b * T_ + m0) * H_ + h) * HD_;
        const int r = tid >> 3;
        const int c = (tid & 7) * 8;
        const uint32_t soff = (uint32_t)(r * ASTR + c) * 2;
#pragma unroll
        for (int it = 0; it < 4; it++) {
            uint4 a = *(const uint4*)(qh + (size_t)(it * 32 + r) * (H_ * HD_) + c);
            STS128(sQhi + it * 32 * ASTR * 2 + soff, a);
            uint4 bb = *(const uint4*)(ql + (size_t)(it * 32 + r) * (H_ * HD_) + c);
            STS128(sQlo + it * 32 * ASTR * 2 + soff, bb);
        }
    }
    __syncthreads();

    uint32_t qhf[4][4], qlf[4][4];
    {
        const uint32_t a_off = (uint32_t)((w * 16 + (lane & 15)) * ASTR * 2
                                          + (lane >> 4) * 16);
#pragma unroll
        for (int ks = 0; ks < 4; ks++) {
            ldsm_x4(qhf[ks], sQhi + a_off + ks * 32);
            ldsm_x4(qlf[ks], sQlo + a_off + ks * 32);
        }
    }

    float o[8][4];
#pragma unroll
    for (int nt = 0; nt < 8; nt++)
#pragma unroll
        for (int e = 0; e < 4; e++) o[nt][e] = 0.f;
    float mrow[2] = {-INFINITY, -INFINITY};
    float lrow[2] = {0.f, 0.f};

    const __nv_bfloat16* khb = khi + ((size_t)b * T_ * G_ + g) * HD_;
    const __nv_bfloat16* klb = klo + ((size_t)b * T_ * G_ + g) * HD_;
    const __nv_bfloat16* vhb = vth + (size_t)(b * G_ + g) * HD_ * T_;
    const __nv_bfloat16* vlb = vtl + (size_t)(b * G_ + g) * HD_ * T_;

    const int rloc = w * 16 + (lane >> 2);

    for (int n0 = 0; n0 < m0 + 128; n0 += 64) {
        {
            const int r = tid >> 3;
            const int c = (tid & 7) * 8;
            const uint32_t soff = (uint32_t)(r * ASTR + c) * 2;
#pragma unroll
            for (int it = 0; it < 2; it++) {
                const int rr = it * 32 + r;
                const uint32_t so = soff + it * 32 * ASTR * 2;
                uint4 a = *(const uint4*)(khb + (size_t)(n0 + rr) * (G_ * HD_) + c);
                STS128(sKhi + so, a);
                uint4 bb = *(const uint4*)(klb + (size_t)(n0 + rr) * (G_ * HD_) + c);
                STS128(sKlo + so, bb);
                uint4 cc = *(const uint4*)(vhb + (size_t)rr * T_ + n0 + c);
                STS128(sVhi + so, cc);
                uint4 dd = *(const uint4*)(vlb + (size_t)rr * T_ + n0 + c);
                STS128(sVlo + so, dd);
            }
        }
        __syncthreads();

        const bool skip = (n0 > m0 + w * 16 + 15);
        if (!skip) {
            const bool needm = (n0 + 63 > m0 + w * 16);

            float s[8][4];
#pragma unroll
            for (int nt = 0; nt < 8; nt++) {
#pragma unroll
                for (int e = 0; e < 4; e++) s[nt][e] = 0.f;
                const uint32_t bo = (uint32_t)((nt * 8 + (lane & 7)) * ASTR * 2
                                               + ((lane >> 3) & 1) * 16);
#pragma unroll
                for (int ks = 0; ks < 4; ks++) {
                    uint32_t bh[2], bl[2];
                    ldsm_x2(bh, sKhi + bo + ks * 32);
                    ldsm_x2(bl, sKlo + bo + ks * 32);
                    mma_bf16(s[nt], qhf[ks], bh);
                    mma_bf16(s[nt], qhf[ks], bl);
                    mma_bf16(s[nt], qlf[ks], bh);
                }
            }

            const int grow0 = m0 + rloc;
            const int grow1 = grow0 + 8;
            float mx0 = -INFINITY, mx1 = -INFINITY;
#pragma unroll
            for (int nt = 0; nt < 8; nt++) {
                const int col = n0 + nt * 8 + (lane & 3) * 2;
#pragma unroll
                for (int e = 0; e < 2; e++) {
                    float v = s[nt][e] * SC_LOG2E;
                    if (needm && (col + e > grow0)) v = -1e30f;
                    s[nt][e] = v;
                    mx0 = fmaxf(mx0, v);
                }
#pragma unroll
                for (int e = 2; e < 4; e++) {
                    float v = s[nt][e] * SC_LOG2E;
                    if (needm && (col + e - 2 > grow1)) v = -1e30f;
                    s[nt][e] = v;
                    mx1 = fmaxf(mx1, v);
                }
            }
            mx0 = fmaxf(mx0, __shfl_xor_sync(0xffffffffu, mx0, 1));
            mx0 = fmaxf(mx0, __shfl_xor_sync(0xffffffffu, mx0, 2));
            mx1 = fmaxf(mx1, __shfl_xor_sync(0xffffffffu, mx1, 1));
            mx1 = fmaxf(mx1, __shfl_xor_sync(0xffffffffu, mx1, 2));

            const float mn0 = fmaxf(mrow[0], mx0);
            const float mn1 = fmaxf(mrow[1], mx1);
            const float c0 = ex2(mrow[0] - mn0);
            const float c1 = ex2(mrow[1] - mn1);
            mrow[0] = mn0; mrow[1] = mn1;

            float s0 = 0.f, s1 = 0.f;
#pragma unroll
            for (int nt = 0; nt < 8; nt++) {
                float p0 = ex2(s[nt][0] - mn0);
                float p1 = ex2(s[nt][1] - mn0);
                float p2 = ex2(s[nt][2] - mn1);
                float p3 = ex2(s[nt][3] - mn1);
                s[nt][0] = p0; s[nt][1] = p1; s[nt][2] = p2; s[nt][3] = p3;
                s0 += p0 + p1; s1 += p2 + p3;
            }
            s0 += __shfl_xor_sync(0xffffffffu, s0, 1);
            s0 += __shfl_xor_sync(0xffffffffu, s0, 2);
            s1 += __shfl_xor_sync(0xffffffffu, s1, 1);
            s1 += __shfl_xor_sync(0xffffffffu, s1, 2);
            lrow[0] = lrow[0] * c0 + s0;
            lrow[1] = lrow[1] * c1 + s1;

#pragma unroll
            for (int nt = 0; nt < 8; nt++) {
                o[nt][0] *= c0; o[nt][1] *= c0;
                o[nt][2] *= c1; o[nt][3] *= c1;
            }

            uint32_t aph[4][4], apl[4][4];
#pragma unroll
            for (int ks = 0; ks < 4; ks++) {
                packhl(s[2 * ks][0],     s[2 * ks][1],     aph[ks][0], apl[ks][0]);
                packhl(s[2 * ks][2],     s[2 * ks][3],     aph[ks][1], apl[ks][1]);
                packhl(s[2 * ks + 1][0], s[2 * ks + 1][1], aph[ks][2], apl[ks][2]);
                packhl(s[2 * ks + 1][2], s[2 * ks + 1][3], aph[ks][3], apl[ks][3]);
            }

#pragma unroll
            for (int nt = 0; nt < 8; nt++) {
                const uint32_t bo = (uint32_t)((nt * 8 + (lane & 7)) * ASTR * 2
                                               + ((lane >> 3) & 1) * 16);
#pragma unroll
                for (int ks = 0; ks < 4; ks++) {
                    uint32_t vh[2], vl[2];
                    ldsm_x2(vh, sVhi + bo + ks * 32);
                    ldsm_x2(vl, sVlo + bo + ks * 32);
                    mma_bf16(o[nt], aph[ks], vh);
                    mma_bf16(o[nt], aph[ks], vl);
                    mma_bf16(o[nt], apl[ks], vh);
                }
            }
        }
        __syncthreads();
    }

    // ---- epilogue: normalize, split to bf16 hi/lo, store ----
    const float i0 = 1.f / lrow[0];
    const float i1 = 1.f / lrow[1];
    const int grow = m0 + rloc;
    const size_t base0 = (size_t)(b * T_ + grow) * D_ + h * HD_ + (lane & 3) * 2;
    const size_t base1 = base0 + 8 * D_;
#pragma unroll
    for (int nt = 0; nt < 8; nt++) {
        uint32_t hi, lo;
        packhl(o[nt][0] * i0, o[nt][1] * i0, hi, lo);
        *(uint32_t*)&obhi[base0 + nt * 8] = hi;
        *(uint32_t*)&oblo[base0 + nt * 8] = lo;
        packhl(o[nt][2] * i1, o[nt][3] * i1, hi, lo);
        *(uint32_t*)&obhi[base1 + nt * 8] = hi;
        *(uint32_t*)&oblo[base1 + nt * 8] = lo;
    }
}

// ---------------------------------------------------------------------------
// Launch
// ---------------------------------------------------------------------------
extern "C" void kernel_launch(void* const* d_in, const int* in_sizes, int n_in,
                              void* d_out, int out_size)
{
    const float* x    = (const float*)d_in[0];
    const float* Wq   = (const float*)d_in[1];
    const float* Wk   = (const float*)d_in[2];
    const float* Wv   = (const float*)d_in[3];
    const float* Wo   = (const float*)d_in[4];
    const float* qn_w = (const float*)d_in[5];
    const float* kn_w = (const float*)d_in[6];
    float* out = (float*)d_out;

    float *qp, *kvp;
    float2* cs;
    __nv_bfloat16 *xhi, *xlo, *wqhi, *wqlo, *wkvhi, *wkvlo, *wohi, *wolo;
    __nv_bfloat16 *qhi, *qlo, *khi, *klo, *vthi, *vtlo, *ohi, *olo;
    cudaGetSymbolAddress((void**)&qp, g_q);
    cudaGetSymbolAddress((void**)&kvp, g_kv);
    cudaGetSymbolAddress((void**)&cs, g_cs);
    cudaGetSymbolAddress((void**)&xhi, g_xhi);
    cudaGetSymbolAddress((void**)&xlo, g_xlo);
    cudaGetSymbolAddress((void**)&wqhi, g_wqhi);
    cudaGetSymbolAddress((void**)&wqlo, g_wqlo);
    cudaGetSymbolAddress((void**)&wkvhi, g_wkvhi);
    cudaGetSymbolAddress((void**)&wkvlo, g_wkvlo);
    cudaGetSymbolAddress((void**)&wohi, g_wohi);
    cudaGetSymbolAddress((void**)&wolo, g_wolo);
    cudaGetSymbolAddress((void**)&qhi, g_qhi);
    cudaGetSymbolAddress((void**)&qlo, g_qlo);
    cudaGetSymbolAddress((void**)&khi, g_khi);
    cudaGetSymbolAddress((void**)&klo, g_klo);
    cudaGetSymbolAddress((void**)&vthi, g_vthi);
    cudaGetSymbolAddress((void**)&vtlo, g_vtlo);
    cudaGetSymbolAddress((void**)&ohi, g_ohi);
    cudaGetSymbolAddress((void**)&olo, g_olo);

    cudaFuncSetAttribute(gemm_bf,
                         cudaFuncAttributeMaxDynamicSharedMemorySize, GEMM_SMEM);
    cudaFuncSetAttribute(attn_mma,
                         cudaFuncAttributeMaxDynamicSharedMemorySize, ATT_SMEM);

    // --- preconversion (x, weights) + rope table ---
    f2bf<<<(BT_ * D_ / 4 + 255) / 256, 256>>>(x, xhi, xlo, BT_ * D_ / 4);
    f2bf<<<(D_ * D_ / 4 + 255) / 256, 256>>>(Wq, wqhi, wqlo, D_ * D_ / 4);
    f2bf<<<(256 * D_ / 4 + 255) / 256, 256>>>(Wk, wkvhi, wkvlo, 256 * D_ / 4);
    f2bf<<<(256 * D_ / 4 + 255) / 256, 256>>>(Wv, wkvhi + 256 * D_,
                                              wkvlo + 256 * D_, 256 * D_ / 4);
    f2bf<<<(D_ * D_ / 4 + 255) / 256, 256>>>(Wo, wohi, wolo, D_ * D_ / 4);
    rope_table<<<T_, 32>>>(cs);

    // --- projections: q and fused k|v ---
    gemm_bf<<<dim3(D_ / 128, BT_ / 128), 256, GEMM_SMEM>>>(
        xhi, xlo, wqhi, wqlo, qp, BT_, D_, D_);
    gemm_bf<<<dim3(KVW / 128, BT_ / 128), 256, GEMM_SMEM>>>(
        xhi, xlo, wkvhi, wkvlo, kvp, BT_, KVW, D_);

    // --- RMSNorm + RoPE -> bf16 hi/lo; V convert+transpose ---
    rmsrope_bf16<<<(BT_ * H_) / 8, 256>>>(qp, D_, qn_w, H_, qhi, qlo, cs);
    rmsrope_bf16<<<(BT_ * G_) / 8, 256>>>(kvp, KVW, kn_w, G_, khi, klo, cs);
    vconv<<<dim3(T_ / 64, G_, B_), 256>>>(kvp + 256, KVW, vthi, vtlo);

    // --- causal GQA flash attention (emits bf16 hi/lo output) ---
    attn_mma<<<dim3(T_ / 128, H_, B_), 256, ATT_SMEM>>>(
        qhi, qlo, khi, klo, vthi, vtlo, ohi, olo);

    // --- output projection ---
    gemm_bf<<<dim3(D_ / 128, BT_ / 128), 256, GEMM_SMEM>>>(
        ohi, olo, wohi, wolo, out, BT_, D_, D_);
}

// round 6
// speedup vs baseline: 1.0673x; 1.0673x over previous
#include <cuda_runtime.h>
#include <cuda_bf16.h>
#include <math.h>
#include <stdint.h>

// ---------------------------------------------------------------------------
// Problem constants
// ---------------------------------------------------------------------------
#define B_   4
#define T_   2048
#define D_   1024
#define H_   16
#define G_   4
#define HD_  64
#define BT_  (B_ * T_)          // 8192
#define KVW  512                 // fused K|V projection width

// ---------------------------------------------------------------------------
// Scratch (device globals -- no allocation allowed)
// ---------------------------------------------------------------------------
__device__ float g_q[BT_ * D_];
__device__ float g_kv[BT_ * KVW];
__device__ float2 g_cs[T_ * 32];

__device__ __nv_bfloat16 g_xhi[BT_ * D_],  g_xlo[BT_ * D_];
__device__ __nv_bfloat16 g_wqhi[D_ * D_],  g_wqlo[D_ * D_];
__device__ __nv_bfloat16 g_wkvhi[KVW * D_], g_wkvlo[KVW * D_];
__device__ __nv_bfloat16 g_wohi[D_ * D_],  g_wolo[D_ * D_];
__device__ __nv_bfloat16 g_qhi[BT_ * D_],  g_qlo[BT_ * D_];
__device__ __nv_bfloat16 g_khi[BT_ * G_ * HD_], g_klo[BT_ * G_ * HD_];
__device__ __nv_bfloat16 g_vthi[B_ * G_ * HD_ * T_], g_vtlo[B_ * G_ * HD_ * T_];
__device__ __nv_bfloat16 g_ohi[BT_ * D_],  g_olo[BT_ * D_];

// ---------------------------------------------------------------------------
// PTX helpers (base sm_100-legal)
// ---------------------------------------------------------------------------
__device__ __forceinline__ uint32_t smem_u32(const void* p) {
    uint32_t a;
    asm("{ .reg .u64 t; cvta.to.shared.u64 t, %1; cvt.u32.u64 %0, t; }"
        : "=r"(a) : "l"(p));
    return a;
}
__device__ __forceinline__ void ldsm_x4(uint32_t (&r)[4], uint32_t addr) {
    asm volatile("ldmatrix.sync.aligned.m8n8.x4.shared.b16 {%0,%1,%2,%3}, [%4];"
                 : "=r"(r[0]), "=r"(r[1]), "=r"(r[2]), "=r"(r[3]) : "r"(addr));
}
__device__ __forceinline__ void ldsm_x2(uint32_t (&r)[2], uint32_t addr) {
    asm volatile("ldmatrix.sync.aligned.m8n8.x2.shared.b16 {%0,%1}, [%2];"
                 : "=r"(r[0]), "=r"(r[1]) : "r"(addr));
}
__device__ __forceinline__ void mma_bf16(float (&d)[4], const uint32_t (&a)[4],
                                         const uint32_t (&b)[2]) {
    asm volatile(
        "mma.sync.aligned.m16n8k16.row.col.f32.bf16.bf16.f32 "
        "{%0,%1,%2,%3}, {%4,%5,%6,%7}, {%8,%9}, {%0,%1,%2,%3};"
        : "+f"(d[0]), "+f"(d[1]), "+f"(d[2]), "+f"(d[3])
        : "r"(a[0]), "r"(a[1]), "r"(a[2]), "r"(a[3]), "r"(b[0]), "r"(b[1]));
}
__device__ __forceinline__ float ex2(float x) {
    float y;
    asm("ex2.approx.ftz.f32 %0, %1;" : "=f"(y) : "f"(x));
    return y;
}
__device__ __forceinline__ void packhl(float x, float y, uint32_t& hi, uint32_t& lo) {
    __nv_bfloat162 h = __floats2bfloat162_rn(x, y);
    float lx = x - __bfloat162float(h.x);
    float ly = y - __bfloat162float(h.y);
    __nv_bfloat162 l2 = __floats2bfloat162_rn(lx, ly);
    hi = *(uint32_t*)&h; lo = *(uint32_t*)&l2;
}
#define STS128(addr, v) \
    asm volatile("st.shared.v4.b32 [%0], {%1,%2,%3,%4};" \
                 :: "r"(addr), "r"((v).x), "r"((v).y), "r"((v).z), "r"((v).w))
#define CP_ASYNC16(dst, src) \
    asm volatile("cp.async.cg.shared.global [%0], [%1], 16;" \
                 :: "r"(dst), "l"(src))
#define CP_COMMIT() asm volatile("cp.async.commit_group;" ::: "memory")
#define CP_WAIT1()  asm volatile("cp.async.wait_group 1;" ::: "memory")
#define CP_WAIT0()  asm volatile("cp.async.wait_group 0;" ::: "memory")

// ---------------------------------------------------------------------------
// fp32 -> bf16 hi/lo converter
// ---------------------------------------------------------------------------
__global__ void __launch_bounds__(256)
f2bf(const float* __restrict__ in, __nv_bfloat16* __restrict__ hi,
     __nv_bfloat16* __restrict__ lo, int n4)
{
    const int i = blockIdx.x * 256 + threadIdx.x;
    if (i >= n4) return;
    float4 v = ((const float4*)in)[i];
    __nv_bfloat162 ha = __floats2bfloat162_rn(v.x, v.y);
    __nv_bfloat162 hb = __floats2bfloat162_rn(v.z, v.w);
    __nv_bfloat162 la = __floats2bfloat162_rn(v.x - __bfloat162float(ha.x),
                                              v.y - __bfloat162float(ha.y));
    __nv_bfloat162 lb = __floats2bfloat162_rn(v.z - __bfloat162float(hb.x),
                                              v.w - __bfloat162float(hb.y));
    uint2 ho = {*(uint32_t*)&ha, *(uint32_t*)&hb};
    uint2 lov = {*(uint32_t*)&la, *(uint32_t*)&lb};
    ((uint2*)hi)[i] = ho;
    ((uint2*)lo)[i] = lov;
}

// ---------------------------------------------------------------------------
// RoPE cos/sin table
// ---------------------------------------------------------------------------
__global__ void rope_table(float2* __restrict__ cs)
{
    const int t = blockIdx.x;
    const int l = threadIdx.x;
    double inv_freq = pow(10000.0, -(double)l / 32.0);
    double ang = (double)t * inv_freq;
    cs[t * 32 + l] = make_float2((float)cos(ang), (float)sin(ang));
}

// ---------------------------------------------------------------------------
// Tensor-core GEMM (HMMA, bf16x3): C[M,N] = A[M,K] @ B[N,K]^T.
// CTA 256x128, 8 warps, warp tile 64x64 (wm 0..3, wn 0..1), KC=32,
// 3-stage cp.async pipeline. B-fragments reused across 4 mt.
// ---------------------------------------------------------------------------
#define KC      32
#define LDT     40                       // padded smem stride (bf16)
#define ATILEB  (256 * LDT * 2)          // 20480 B per A array (hi or lo)
#define BTILEB  (128 * LDT * 2)          // 10240 B per B array
#define STAGEB  (2 * ATILEB + 2 * BTILEB) // 61440 B
#define GEMM_SMEM (3 * STAGEB)           // 184320 B

__global__ void __launch_bounds__(256, 1)
gemm_bf(const __nv_bfloat16* __restrict__ Ahi, const __nv_bfloat16* __restrict__ Alo,
        const __nv_bfloat16* __restrict__ Bhi, const __nv_bfloat16* __restrict__ Blo,
        float* __restrict__ C, int M, int N, int K)
{
    extern __shared__ char smraw[];
    const uint32_t sb = smem_u32(smraw);

    const int tid  = threadIdx.x;
    const int lane = tid & 31;
    const int wid  = tid >> 5;
    const int wm   = wid & 3;            // 0..3 -> 64 rows each
    const int wn   = wid >> 2;           // 0..1 -> 64 cols each
    const int m0 = blockIdx.y * 256;
    const int n0 = blockIdx.x * 128;

    // cp.async mapping: thread -> (row = tid>>2, 16B seg = tid&3)
    const int r0   = tid >> 2;           // 0..63
    const int cseg = (tid & 3) * 8;      // bf16 offset within 32-wide row
    const __nv_bfloat16* pAh = Ahi + (size_t)(m0 + r0) * K + cseg;
    const __nv_bfloat16* pAl = Alo + (size_t)(m0 + r0) * K + cseg;
    const __nv_bfloat16* pBh = Bhi + (size_t)(n0 + r0) * K + cseg;
    const __nv_bfloat16* pBl = Blo + (size_t)(n0 + r0) * K + cseg;
    const uint32_t dA = (uint32_t)(r0 * LDT + cseg) * 2;
    const size_t rstep = (size_t)64 * K;
    const uint32_t dstep = 64 * LDT * 2;

    const uint32_t a_off = (uint32_t)(((wm * 64 + (lane & 15)) * LDT
                                       + (lane >> 4) * 8) * 2);
    const uint32_t b_off = (uint32_t)(((wn * 64 + (lane & 7)) * LDT
                                       + ((lane >> 3) & 1) * 8) * 2);

    float acc[4][8][4];
#pragma unroll
    for (int i = 0; i < 4; i++)
#pragma unroll
        for (int j = 0; j < 8; j++)
#pragma unroll
            for (int e = 0; e < 4; e++) acc[i][j][e] = 0.f;

    const int nch = K / KC;

#define ISSUE(c) do {                                                       \
        const uint32_t st_ = sb + ((c) % 3) * STAGEB;                       \
        const size_t k0_ = (size_t)(c) * KC;                                \
        CP_ASYNC16(st_ + dA,                           pAh + k0_);          \
        CP_ASYNC16(st_ + dA + dstep,                   pAh + k0_ + rstep);  \
        CP_ASYNC16(st_ + dA + 2 * dstep,               pAh + k0_ + 2 * rstep); \
        CP_ASYNC16(st_ + dA + 3 * dstep,               pAh + k0_ + 3 * rstep); \
        CP_ASYNC16(st_ + ATILEB + dA,                  pAl + k0_);          \
        CP_ASYNC16(st_ + ATILEB + dA + dstep,          pAl + k0_ + rstep);  \
        CP_ASYNC16(st_ + ATILEB + dA + 2 * dstep,      pAl + k0_ + 2 * rstep); \
        CP_ASYNC16(st_ + ATILEB + dA + 3 * dstep,      pAl + k0_ + 3 * rstep); \
        CP_ASYNC16(st_ + 2 * ATILEB + dA,              pBh + k0_);          \
        CP_ASYNC16(st_ + 2 * ATILEB + dA + dstep,      pBh + k0_ + rstep);  \
        CP_ASYNC16(st_ + 2 * ATILEB + BTILEB + dA,         pBl + k0_);      \
        CP_ASYNC16(st_ + 2 * ATILEB + BTILEB + dA + dstep, pBl + k0_ + rstep); \
        CP_COMMIT();                                                        \
    } while (0)

    ISSUE(0);
    ISSUE(1);

    for (int c = 0; c < nch; c++) {
        if (c + 2 < nch) CP_WAIT1(); else CP_WAIT0();
        __syncthreads();
        if (c + 2 < nch) ISSUE(c + 2);

        const uint32_t tb  = sb + (c % 3) * STAGEB;
        const uint32_t aHi = tb;
        const uint32_t aLo = tb + ATILEB;
        const uint32_t bHi = tb + 2 * ATILEB;
        const uint32_t bLo = tb + 2 * ATILEB + BTILEB;

#pragma unroll
        for (int ks = 0; ks < 2; ks++) {
            const uint32_t ksb = ks * 32;
            uint32_t ahi[4][4], alo[4][4];
#pragma unroll
            for (int mt = 0; mt < 4; mt++) {
                ldsm_x4(ahi[mt], aHi + a_off + mt * (16 * LDT * 2) + ksb);
                ldsm_x4(alo[mt], aLo + a_off + mt * (16 * LDT * 2) + ksb);
            }
#pragma unroll
            for (int nt = 0; nt < 8; nt++) {
                uint32_t bh[2], bl[2];
                ldsm_x2(bh, bHi + b_off + nt * (8 * LDT * 2) + ksb);
                ldsm_x2(bl, bLo + b_off + nt * (8 * LDT * 2) + ksb);
#pragma unroll
                for (int mt = 0; mt < 4; mt++) {
                    mma_bf16(acc[mt][nt], ahi[mt], bh);
                    mma_bf16(acc[mt][nt], ahi[mt], bl);
                    mma_bf16(acc[mt][nt], alo[mt], bh);
                }
            }
        }
        __syncthreads();
    }
#undef ISSUE

#pragma unroll
    for (int mt = 0; mt < 4; mt++) {
        const int r = m0 + wm * 64 + mt * 16 + (lane >> 2);
#pragma unroll
        for (int nt = 0; nt < 8; nt++) {
            const int cc = n0 + wn * 64 + nt * 8 + (lane & 3) * 2;
            float2 v0 = {acc[mt][nt][0], acc[mt][nt][1]};
            float2 v1 = {acc[mt][nt][2], acc[mt][nt][3]};
            *(float2*)&C[(size_t)r * N + cc]       = v0;
            *(float2*)&C[(size_t)(r + 8) * N + cc] = v1;
        }
    }
}

// ---------------------------------------------------------------------------
// RMSNorm + RoPE (table-based), fp32 in (strided) -> bf16 hi/lo out (packed)
// ---------------------------------------------------------------------------
__global__ void __launch_bounds__(256)
rmsrope_bf16(const float* __restrict__ in, int rowstride,
             const float* __restrict__ w, int nheads,
             __nv_bfloat16* __restrict__ ohi, __nv_bfloat16* __restrict__ olo,
             const float2* __restrict__ cs)
{
    const int lane   = threadIdx.x & 31;
    const int warpid = threadIdx.x >> 5;
    const int row    = blockIdx.x * 8 + warpid;
    const int bt     = row / nheads;
    const int head   = row - bt * nheads;
    const int t      = bt & (T_ - 1);

    const float* p = in + (size_t)bt * rowstride + head * HD_;
    float2 x = *(const float2*)&p[2 * lane];

    float ss = x.x * x.x + x.y * x.y;
#pragma unroll
    for (int o = 16; o > 0; o >>= 1)
        ss += __shfl_xor_sync(0xffffffffu, ss, o);

    float rms = rsqrtf(ss * (1.0f / HD_) + 1e-6f);
    float xn1 = x.x * rms * w[2 * lane];
    float xn2 = x.y * rms * w[2 * lane + 1];

    float2 csv = cs[t * 32 + lane];
    float ox = xn1 * csv.x - xn2 * csv.y;
    float oy = xn2 * csv.x + xn1 * csv.y;

    const size_t idx = (size_t)bt * (nheads * HD_) + head * HD_ + 2 * lane;
    uint32_t hi, lo;
    packhl(ox, oy, hi, lo);
    *(uint32_t*)&ohi[idx] = hi;
    *(uint32_t*)&olo[idx] = lo;
}

// ---------------------------------------------------------------------------
// V convert + transpose: fp32 strided [bt, g*64] -> bf16 hi/lo [b,g,hd,T]
// ---------------------------------------------------------------------------
__global__ void __launch_bounds__(256)
vconv(const float* __restrict__ v, int rowstride,
      __nv_bfloat16* __restrict__ vth, __nv_bfloat16* __restrict__ vtl)
{
    __shared__ float s[64][65];
    const int t0 = blockIdx.x * 64;
    const int g  = blockIdx.y;
    const int b  = blockIdx.z;
    const int tid = threadIdx.x;

#pragma unroll
    for (int it = 0; it < 4; it++) {
        int tr = it * 16 + (tid >> 4);
        int c4 = (tid & 15) * 4;
        float4 val = *(const float4*)&v[(size_t)(b * T_ + t0 + tr) * rowstride
                                        + g * HD_ + c4];
        s[tr][c4 + 0] = val.x; s[tr][c4 + 1] = val.y;
        s[tr][c4 + 2] = val.z; s[tr][c4 + 3] = val.w;
    }
    __syncthreads();

    const int hd  = tid >> 2;
    const int seg = tid & 3;
    __nv_bfloat16 hi[16], lo[16];
#pragma unroll
    for (int j = 0; j < 16; j++) {
        float x = s[seg * 16 + j][hd];
        __nv_bfloat16 h = __float2bfloat16(x);
        hi[j] = h;
        lo[j] = __float2bfloat16(x - __bfloat162float(h));
    }
    const size_t ob = ((size_t)(b * G_ + g) * HD_ + hd) * T_ + t0 + seg * 16;
    *(uint4*)&vth[ob]     = *(uint4*)&hi[0];
    *(uint4*)&vth[ob + 8] = *(uint4*)&hi[8];
    *(uint4*)&vtl[ob]     = *(uint4*)&lo[0];
    *(uint4*)&vtl[ob + 8] = *(uint4*)&lo[8];
}

// ---------------------------------------------------------------------------
// Causal GQA flash attention, HMMA bf16x3.
// CTA = 128 q-rows, 4 warps (32 rows each = 2 x 16-row MMA groups),
// 64-key tiles; K/V fragments loaded once, reused across both groups.
// ---------------------------------------------------------------------------
#define ASTR  72
#define ATILE (64 * ASTR * 2)
#define AQT   (128 * ASTR * 2)
#define ATT_SMEM (2 * AQT + 4 * ATILE)   // 73728 B
#define SC_LOG2E 0.18033688011112042f

__global__ void __launch_bounds__(128)
attn_mma(const __nv_bfloat16* __restrict__ qhi, const __nv_bfloat16* __restrict__ qlo,
         const __nv_bfloat16* __restrict__ khi, const __nv_bfloat16* __restrict__ klo,
         const __nv_bfloat16* __restrict__ vth, const __nv_bfloat16* __restrict__ vtl,
         __nv_bfloat16* __restrict__ obhi, __nv_bfloat16* __restrict__ oblo)
{
    extern __shared__ char smraw[];
    const uint32_t sb   = smem_u32(smraw);
    const uint32_t sQhi = sb;
    const uint32_t sQlo = sb + AQT;
    const uint32_t sKhi = sb + 2 * AQT;
    const uint32_t sKlo = sKhi + ATILE;
    const uint32_t sVhi = sKlo + ATILE;
    const uint32_t sVlo = sVhi + ATILE;

    const int tid  = threadIdx.x;
    const int lane = tid & 31;
    const int w    = tid >> 5;            // 0..3
    const int mblk = gridDim.x - 1 - blockIdx.x;
    const int m0   = mblk * 128;
    const int h    = blockIdx.y;
    const int b    = blockIdx.z;
    const int g    = h >> 2;

    // ---- stage Q tile (128 rows) ----
    {
        const __nv_bfloat16* qh = qhi + ((size_t)(b * T_ + m0) * H_ + h) * HD_;
        const __nv_bfloat16* ql = qlo + ((size_t)(b * T_ + m0) * H_ + h) * HD_;
        const int r = tid >> 3;           // 0..15
        const int c = (tid & 7) * 8;
        const uint32_t soff = (uint32_t)(r * ASTR + c) * 2;
#pragma unroll
        for (int it = 0; it < 8; it++) {
            uint4 a = *(const uint4*)(qh + (size_t)(it * 16 + r) * (H_ * HD_) + c);
            STS128(sQhi + it * 16 * ASTR * 2 + soff, a);
            uint4 bb = *(const uint4*)(ql + (size_t)(it * 16 + r) * (H_ * HD_) + c);
            STS128(sQlo + it * 16 * ASTR * 2 + soff, bb);
        }
    }
    __syncthreads();

    // ---- Q fragments: 2 groups of 16 rows ----
    uint32_t qhf[2][4][4], qlf[2][4][4];
#pragma unroll
    for (int mt = 0; mt < 2; mt++) {
        const uint32_t a_off = (uint32_t)((w * 32 + mt * 16 + (lane & 15)) * ASTR * 2
                                          + (lane >> 4) * 16);
#pragma unroll
        for (int ks = 0; ks < 4; ks++) {
            ldsm_x4(qhf[mt][ks], sQhi + a_off + ks * 32);
            ldsm_x4(qlf[mt][ks], sQlo + a_off + ks * 32);
        }
    }

    float o[2][8][4];
#pragma unroll
    for (int mt = 0; mt < 2; mt++)
#pragma unroll
        for (int nt = 0; nt < 8; nt++)
#pragma unroll
            for (int e = 0; e < 4; e++) o[mt][nt][e] = 0.f;
    float mrow[2][2] = {{-INFINITY, -INFINITY}, {-INFINITY, -INFINITY}};
    float lrow[2][2] = {{0.f, 0.f}, {0.f, 0.f}};

    const __nv_bfloat16* khb = khi + ((size_t)b * T_ * G_ + g) * HD_;
    const __nv_bfloat16* klb = klo + ((size_t)b * T_ * G_ + g) * HD_;
    const __nv_bfloat16* vhb = vth + (size_t)(b * G_ + g) * HD_ * T_;
    const __nv_bfloat16* vlb = vtl + (size_t)(b * G_ + g) * HD_ * T_;

    for (int n0 = 0; n0 < m0 + 128; n0 += 64) {
        // ---- load K/V tiles (128 threads) ----
        {
            const int r = tid >> 3;       // 0..15
            const int c = (tid & 7) * 8;
            const uint32_t soff = (uint32_t)(r * ASTR + c) * 2;
#pragma unroll
            for (int it = 0; it < 4; it++) {
                const int rr = it * 16 + r;
                const uint32_t so = soff + it * 16 * ASTR * 2;
                uint4 a = *(const uint4*)(khb + (size_t)(n0 + rr) * (G_ * HD_) + c);
                STS128(sKhi + so, a);
                uint4 bb = *(const uint4*)(klb + (size_t)(n0 + rr) * (G_ * HD_) + c);
                STS128(sKlo + so, bb);
                uint4 cc = *(const uint4*)(vhb + (size_t)rr * T_ + n0 + c);
                STS128(sVhi + so, cc);
                uint4 dd = *(const uint4*)(vlb + (size_t)rr * T_ + n0 + c);
                STS128(sVlo + so, dd);
            }
        }
        __syncthreads();

        const bool skip = (n0 > m0 + w * 32 + 31);
        if (!skip) {
            const bool needm = (n0 + 63 > m0 + w * 32);

            // ---- S = Q K^T (bf16x3); K frags loaded once, reused by both mt ----
            float s[2][8][4];
#pragma unroll
            for (int mt = 0; mt < 2; mt++)
#pragma unroll
                for (int nt = 0; nt < 8; nt++)
#pragma unroll
                    for (int e = 0; e < 4; e++) s[mt][nt][e] = 0.f;

#pragma unroll
            for (int ks = 0; ks < 4; ks++) {
#pragma unroll
                for (int nt = 0; nt < 8; nt++) {
                    const uint32_t bo = (uint32_t)((nt * 8 + (lane & 7)) * ASTR * 2
                                                   + ((lane >> 3) & 1) * 16) + ks * 32;
                    uint32_t bh[2], bl[2];
                    ldsm_x2(bh, sKhi + bo);
                    ldsm_x2(bl, sKlo + bo);
#pragma unroll
                    for (int mt = 0; mt < 2; mt++) {
                        mma_bf16(s[mt][nt], qhf[mt][ks], bh);
                        mma_bf16(s[mt][nt], qhf[mt][ks], bl);
                        mma_bf16(s[mt][nt], qlf[mt][ks], bh);
                    }
                }
            }

            // ---- per-group softmax; s dies into P fragments ----
            uint32_t aph[2][4][4], apl[2][4][4];
#pragma unroll
            for (int mt = 0; mt < 2; mt++) {
                const int grow0 = m0 + w * 32 + mt * 16 + (lane >> 2);
                const int grow1 = grow0 + 8;
                float mx0 = -INFINITY, mx1 = -INFINITY;
#pragma unroll
                for (int nt = 0; nt < 8; nt++) {
                    const int col = n0 + nt * 8 + (lane & 3) * 2;
#pragma unroll
                    for (int e = 0; e < 2; e++) {
                        float v = s[mt][nt][e] * SC_LOG2E;
                        if (needm && (col + e > grow0)) v = -1e30f;
                        s[mt][nt][e] = v;
                        mx0 = fmaxf(mx0, v);
                    }
#pragma unroll
                    for (int e = 2; e < 4; e++) {
                        float v = s[mt][nt][e] * SC_LOG2E;
                        if (needm && (col + e - 2 > grow1)) v = -1e30f;
                        s[mt][nt][e] = v;
                        mx1 = fmaxf(mx1, v);
                    }
                }
                mx0 = fmaxf(mx0, __shfl_xor_sync(0xffffffffu, mx0, 1));
                mx0 = fmaxf(mx0, __shfl_xor_sync(0xffffffffu, mx0, 2));
                mx1 = fmaxf(mx1, __shfl_xor_sync(0xffffffffu, mx1, 1));
                mx1 = fmaxf(mx1, __shfl_xor_sync(0xffffffffu, mx1, 2));

                const float mn0 = fmaxf(mrow[mt][0], mx0);
                const float mn1 = fmaxf(mrow[mt][1], mx1);
                const float c0 = ex2(mrow[mt][0] - mn0);
                const float c1 = ex2(mrow[mt][1] - mn1);
                mrow[mt][0] = mn0; mrow[mt][1] = mn1;

                float s0 = 0.f, s1 = 0.f;
#pragma unroll
                for (int nt = 0; nt < 8; nt++) {
                    float p0 = ex2(s[mt][nt][0] - mn0);
                    float p1 = ex2(s[mt][nt][1] - mn0);
                    float p2 = ex2(s[mt][nt][2] - mn1);
                    float p3 = ex2(s[mt][nt][3] - mn1);
                    s[mt][nt][0] = p0; s[mt][nt][1] = p1;
                    s[mt][nt][2] = p2; s[mt][nt][3] = p3;
                    s0 += p0 + p1; s1 += p2 + p3;
                }
                s0 += __shfl_xor_sync(0xffffffffu, s0, 1);
                s0 += __shfl_xor_sync(0xffffffffu, s0, 2);
                s1 += __shfl_xor_sync(0xffffffffu, s1, 1);
                s1 += __shfl_xor_sync(0xffffffffu, s1, 2);
                lrow[mt][0] = lrow[mt][0] * c0 + s0;
                lrow[mt][1] = lrow[mt][1] * c1 + s1;

#pragma unroll
                for (int nt = 0; nt < 8; nt++) {
                    o[mt][nt][0] *= c0; o[mt][nt][1] *= c0;
                    o[mt][nt][2] *= c1; o[mt][nt][3] *= c1;
                }
#pragma unroll
                for (int ks = 0; ks < 4; ks++) {
                    packhl(s[mt][2 * ks][0],     s[mt][2 * ks][1],
                           aph[mt][ks][0], apl[mt][ks][0]);
                    packhl(s[mt][2 * ks][2],     s[mt][2 * ks][3],
                           aph[mt][ks][1], apl[mt][ks][1]);
                    packhl(s[mt][2 * ks + 1][0], s[mt][2 * ks + 1][1],
                           aph[mt][ks][2], apl[mt][ks][2]);
                    packhl(s[mt][2 * ks + 1][2], s[mt][2 * ks + 1][3],
                           aph[mt][ks][3], apl[mt][ks][3]);
                }
            }

            // ---- O += P V (bf16x3); V frags loaded once, reused by both mt ----
#pragma unroll
            for (int nt = 0; nt < 8; nt++) {
#pragma unroll
                for (int ks = 0; ks < 4; ks++) {
                    const uint32_t bo = (uint32_t)((nt * 8 + (lane & 7)) * ASTR * 2
                                                   + ((lane >> 3) & 1) * 16) + ks * 32;
                    uint32_t vh[2], vl[2];
                    ldsm_x2(vh, sVhi + bo);
                    ldsm_x2(vl, sVlo + bo);
#pragma unroll
                    for (int mt = 0; mt < 2; mt++) {
                        mma_bf16(o[mt][nt], aph[mt][ks], vh);
                        mma_bf16(o[mt][nt], aph[mt][ks], vl);
                        mma_bf16(o[mt][nt], apl[mt][ks], vh);
                    }
                }
            }
        }
        __syncthreads();
    }

    // ---- epilogue: normalize, split to bf16 hi/lo, store ----
#pragma unroll
    for (int mt = 0; mt < 2; mt++) {
        const float i0 = 1.f / lrow[mt][0];
        const float i1 = 1.f / lrow[mt][1];
        const int grow = m0 + w * 32 + mt * 16 + (lane >> 2);
        const size_t base0 = (size_t)(b * T_ + grow) * D_ + h * HD_ + (lane & 3) * 2;
        const size_t base1 = base0 + 8 * D_;
#pragma unroll
        for (int nt = 0; nt < 8; nt++) {
            uint32_t hi, lo;
            packhl(o[mt][nt][0] * i0, o[mt][nt][1] * i0, hi, lo);
            *(uint32_t*)&obhi[base0 + nt * 8] = hi;
            *(uint32_t*)&oblo[base0 + nt * 8] = lo;
            packhl(o[mt][nt][2] * i1, o[mt][nt][3] * i1, hi, lo);
            *(uint32_t*)&obhi[base1 + nt * 8] = hi;
            *(uint32_t*)&oblo[base1 + nt * 8] = lo;
        }
    }
}

// ---------------------------------------------------------------------------
// Launch
// ---------------------------------------------------------------------------
extern "C" void kernel_launch(void* const* d_in, const int* in_sizes, int n_in,
                              void* d_out, int out_size)
{
    const float* x    = (const float*)d_in[0];
    const float* Wq   = (const float*)d_in[1];
    const float* Wk   = (const float*)d_in[2];
    const float* Wv   = (const float*)d_in[3];
    const float* Wo   = (const float*)d_in[4];
    const float* qn_w = (const float*)d_in[5];
    const float* kn_w = (const float*)d_in[6];
    float* out = (float*)d_out;

    float *qp, *kvp;
    float2* cs;
    __nv_bfloat16 *xhi, *xlo, *wqhi, *wqlo, *wkvhi, *wkvlo, *wohi, *wolo;
    __nv_bfloat16 *qhi, *qlo, *khi, *klo, *vthi, *vtlo, *ohi, *olo;
    cudaGetSymbolAddress((void**)&qp, g_q);
    cudaGetSymbolAddress((void**)&kvp, g_kv);
    cudaGetSymbolAddress((void**)&cs, g_cs);
    cudaGetSymbolAddress((void**)&xhi, g_xhi);
    cudaGetSymbolAddress((void**)&xlo, g_xlo);
    cudaGetSymbolAddress((void**)&wqhi, g_wqhi);
    cudaGetSymbolAddress((void**)&wqlo, g_wqlo);
    cudaGetSymbolAddress((void**)&wkvhi, g_wkvhi);
    cudaGetSymbolAddress((void**)&wkvlo, g_wkvlo);
    cudaGetSymbolAddress((void**)&wohi, g_wohi);
    cudaGetSymbolAddress((void**)&wolo, g_wolo);
    cudaGetSymbolAddress((void**)&qhi, g_qhi);
    cudaGetSymbolAddress((void**)&qlo, g_qlo);
    cudaGetSymbolAddress((void**)&khi, g_khi);
    cudaGetSymbolAddress((void**)&klo, g_klo);
    cudaGetSymbolAddress((void**)&vthi, g_vthi);
    cudaGetSymbolAddress((void**)&vtlo, g_vtlo);
    cudaGetSymbolAddress((void**)&ohi, g_ohi);
    cudaGetSymbolAddress((void**)&olo, g_olo);

    cudaFuncSetAttribute(gemm_bf,
                         cudaFuncAttributeMaxDynamicSharedMemorySize, GEMM_SMEM);
    cudaFuncSetAttribute(attn_mma,
                         cudaFuncAttributeMaxDynamicSharedMemorySize, ATT_SMEM);

    // --- preconversion + rope table ---
    f2bf<<<(BT_ * D_ / 4 + 255) / 256, 256>>>(x, xhi, xlo, BT_ * D_ / 4);
    f2bf<<<(D_ * D_ / 4 + 255) / 256, 256>>>(Wq, wqhi, wqlo, D_ * D_ / 4);
    f2bf<<<(256 * D_ / 4 + 255) / 256, 256>>>(Wk, wkvhi, wkvlo, 256 * D_ / 4);
    f2bf<<<(256 * D_ / 4 + 255) / 256, 256>>>(Wv, wkvhi + 256 * D_,
                                              wkvlo + 256 * D_, 256 * D_ / 4);
    f2bf<<<(D_ * D_ / 4 + 255) / 256, 256>>>(Wo, wohi, wolo, D_ * D_ / 4);
    rope_table<<<T_, 32>>>(cs);

    // --- projections: q and fused k|v (CTA 256x128) ---
    gemm_bf<<<dim3(D_ / 128, BT_ / 256), 256, GEMM_SMEM>>>(
        xhi, xlo, wqhi, wqlo, qp, BT_, D_, D_);
    gemm_bf<<<dim3(KVW / 128, BT_ / 256), 256, GEMM_SMEM>>>(
        xhi, xlo, wkvhi, wkvlo, kvp, BT_, KVW, D_);

    // --- RMSNorm + RoPE -> bf16 hi/lo; V convert+transpose ---
    rmsrope_bf16<<<(BT_ * H_) / 8, 256>>>(qp, D_, qn_w, H_, qhi, qlo, cs);
    rmsrope_bf16<<<(BT_ * G_) / 8, 256>>>(kvp, KVW, kn_w, G_, khi, klo, cs);
    vconv<<<dim3(T_ / 64, G_, B_), 256>>>(kvp + 256, KVW, vthi, vtlo);

    // --- causal GQA flash attention (4 warps, 32 rows/warp) ---
    attn_mma<<<dim3(T_ / 128, H_, B_), 128, ATT_SMEM>>>(
        qhi, qlo, khi, klo, vthi, vtlo, ohi, olo);

    // --- output projection ---
    gemm_bf<<<dim3(D_ / 128, BT_ / 256), 256, GEMM_SMEM>>>(
        ohi, olo, wohi, wolo, out, BT_, D_, D_);
}

// round 7
// speedup vs baseline: 1.5263x; 1.4300x over previous
#include <cuda_runtime.h>
#include <cuda_fp16.h>
#include <math.h>
#include <stdint.h>

// ---------------------------------------------------------------------------
// Problem constants
// ---------------------------------------------------------------------------
#define B_   4
#define T_   2048
#define D_   1024
#define H_   16
#define G_   4
#define HD_  64
#define BT_  (B_ * T_)          // 8192
#define KVW  512                 // fused K|V projection width

// ---------------------------------------------------------------------------
// Scratch (device globals -- no allocation allowed)
// ---------------------------------------------------------------------------
__device__ float g_q[BT_ * D_];
__device__ float g_kv[BT_ * KVW];
__device__ float2 g_cs[T_ * 32];

__device__ __half g_x16[BT_ * D_];                       // A of proj GEMMs
__device__ __half g_wqhi[D_ * D_],  g_wqlo[D_ * D_];
__device__ __half g_wkvhi[KVW * D_], g_wkvlo[KVW * D_];
__device__ __half g_wohi[D_ * D_],  g_wolo[D_ * D_];
__device__ __half g_q16[BT_ * D_];                       // Q (single fp16)
__device__ __half g_khi[BT_ * G_ * HD_], g_klo[BT_ * G_ * HD_];
__device__ __half g_vthi[B_ * G_ * HD_ * T_], g_vtlo[B_ * G_ * HD_ * T_];
__device__ __half g_o16[BT_ * D_];                       // attn out (single)

// ---------------------------------------------------------------------------
// PTX helpers (base sm_100-legal)
// ---------------------------------------------------------------------------
__device__ __forceinline__ uint32_t smem_u32(const void* p) {
    uint32_t a;
    asm("{ .reg .u64 t; cvta.to.shared.u64 t, %1; cvt.u32.u64 %0, t; }"
        : "=r"(a) : "l"(p));
    return a;
}
__device__ __forceinline__ void ldsm_x4(uint32_t (&r)[4], uint32_t addr) {
    asm volatile("ldmatrix.sync.aligned.m8n8.x4.shared.b16 {%0,%1,%2,%3}, [%4];"
                 : "=r"(r[0]), "=r"(r[1]), "=r"(r[2]), "=r"(r[3]) : "r"(addr));
}
__device__ __forceinline__ void ldsm_x2(uint32_t (&r)[2], uint32_t addr) {
    asm volatile("ldmatrix.sync.aligned.m8n8.x2.shared.b16 {%0,%1}, [%2];"
                 : "=r"(r[0]), "=r"(r[1]) : "r"(addr));
}
__device__ __forceinline__ void mma_f16(float (&d)[4], const uint32_t (&a)[4],
                                        const uint32_t (&b)[2]) {
    asm volatile(
        "mma.sync.aligned.m16n8k16.row.col.f32.f16.f16.f32 "
        "{%0,%1,%2,%3}, {%4,%5,%6,%7}, {%8,%9}, {%0,%1,%2,%3};"
        : "+f"(d[0]), "+f"(d[1]), "+f"(d[2]), "+f"(d[3])
        : "r"(a[0]), "r"(a[1]), "r"(a[2]), "r"(a[3]), "r"(b[0]), "r"(b[1]));
}
__device__ __forceinline__ float ex2(float x) {
    float y;
    asm("ex2.approx.ftz.f32 %0, %1;" : "=f"(y) : "f"(x));
    return y;
}
__device__ __forceinline__ uint32_t pack_h2(float x, float y) {
    __half2 h = __floats2half2_rn(x, y);
    return *(uint32_t*)&h;
}
__device__ __forceinline__ void packhl_h(float x, float y,
                                         uint32_t& hi, uint32_t& lo) {
    __half2 h = __floats2half2_rn(x, y);
    float lx = x - __half2float(__low2half(h));
    float ly = y - __half2float(__high2half(h));
    __half2 l = __floats2half2_rn(lx, ly);
    hi = *(uint32_t*)&h; lo = *(uint32_t*)&l;
}
#define STS128(addr, v) \
    asm volatile("st.shared.v4.b32 [%0], {%1,%2,%3,%4};" \
                 :: "r"(addr), "r"((v).x), "r"((v).y), "r"((v).z), "r"((v).w))
#define CP_ASYNC16(dst, src) \
    asm volatile("cp.async.cg.shared.global [%0], [%1], 16;" \
                 :: "r"(dst), "l"(src))
#define CP_COMMIT() asm volatile("cp.async.commit_group;" ::: "memory")
#define CP_WAIT1()  asm volatile("cp.async.wait_group 1;" ::: "memory")
#define CP_WAIT0()  asm volatile("cp.async.wait_group 0;" ::: "memory")

// ---------------------------------------------------------------------------
// Converters
// ---------------------------------------------------------------------------
__global__ void __launch_bounds__(256)
f2h_single(const float* __restrict__ in, __half* __restrict__ out, int n4)
{
    const int i = blockIdx.x * 256 + threadIdx.x;
    if (i >= n4) return;
    float4 v = ((const float4*)in)[i];
    uint2 o = {pack_h2(v.x, v.y), pack_h2(v.z, v.w)};
    ((uint2*)out)[i] = o;
}

__global__ void __launch_bounds__(256)
f2h_split(const float* __restrict__ in, __half* __restrict__ hi,
          __half* __restrict__ lo, int n4)
{
    const int i = blockIdx.x * 256 + threadIdx.x;
    if (i >= n4) return;
    float4 v = ((const float4*)in)[i];
    uint32_t h0, h1, l0, l1;
    packhl_h(v.x, v.y, h0, l0);
    packhl_h(v.z, v.w, h1, l1);
    uint2 ho = {h0, h1}, lv = {l0, l1};
    ((uint2*)hi)[i] = ho;
    ((uint2*)lo)[i] = lv;
}

__global__ void rope_table(float2* __restrict__ cs)
{
    const int t = blockIdx.x;
    const int l = threadIdx.x;
    double inv_freq = pow(10000.0, -(double)l / 32.0);
    double ang = (double)t * inv_freq;
    cs[t * 32 + l] = make_float2((float)cos(ang), (float)sin(ang));
}

// ---------------------------------------------------------------------------
// Tensor-core GEMM (HMMA fp16, 2-pass): C[M,N] = A16[M,K] @ (Bhi+Blo)[N,K]^T.
// CTA 256x128, 8 warps, warp tile 64x64, KC=32, 3-stage cp.async pipeline.
// ---------------------------------------------------------------------------
#define KC      32
#define LDT     40                        // padded smem stride (halfs)
#define ATILEB  (256 * LDT * 2)           // 20480 B (A single)
#define BTILEB  (128 * LDT * 2)           // 10240 B (per B array)
#define STAGEB  (ATILEB + 2 * BTILEB)     // 40960 B
#define GEMM_SMEM (3 * STAGEB)            // 122880 B

__global__ void __launch_bounds__(256, 1)
gemm_h2(const __half* __restrict__ A16,
        const __half* __restrict__ Bhi, const __half* __restrict__ Blo,
        float* __restrict__ C, int M, int N, int K)
{
    extern __shared__ char smraw[];
    const uint32_t sb = smem_u32(smraw);

    const int tid  = threadIdx.x;
    const int lane = tid & 31;
    const int wid  = tid >> 5;
    const int wm   = wid & 3;             // 0..3 -> 64 rows each
    const int wn   = wid >> 2;            // 0..1 -> 64 cols each
    const int m0 = blockIdx.y * 256;
    const int n0 = blockIdx.x * 128;

    const int r0   = tid >> 2;            // 0..63
    const int cseg = (tid & 3) * 8;
    const __half* pA = A16 + (size_t)(m0 + r0) * K + cseg;
    const __half* pBh = Bhi + (size_t)(n0 + r0) * K + cseg;
    const __half* pBl = Blo + (size_t)(n0 + r0) * K + cseg;
    const uint32_t dA = (uint32_t)(r0 * LDT + cseg) * 2;
    const size_t rstep = (size_t)64 * K;
    const uint32_t dstep = 64 * LDT * 2;

    const uint32_t a_off = (uint32_t)(((wm * 64 + (lane & 15)) * LDT
                                       + (lane >> 4) * 8) * 2);
    const uint32_t b_off = (uint32_t)(((wn * 64 + (lane & 7)) * LDT
                                       + ((lane >> 3) & 1) * 8) * 2);

    float acc[4][8][4];
#pragma unroll
    for (int i = 0; i < 4; i++)
#pragma unroll
        for (int j = 0; j < 8; j++)
#pragma unroll
            for (int e = 0; e < 4; e++) acc[i][j][e] = 0.f;

    const int nch = K / KC;

#define ISSUE(c) do {                                                       \
        const uint32_t st_ = sb + ((c) % 3) * STAGEB;                       \
        const size_t k0_ = (size_t)(c) * KC;                                \
        CP_ASYNC16(st_ + dA,               pA + k0_);                       \
        CP_ASYNC16(st_ + dA + dstep,       pA + k0_ + rstep);               \
        CP_ASYNC16(st_ + dA + 2 * dstep,   pA + k0_ + 2 * rstep);           \
        CP_ASYNC16(st_ + dA + 3 * dstep,   pA + k0_ + 3 * rstep);           \
        CP_ASYNC16(st_ + ATILEB + dA,              pBh + k0_);              \
        CP_ASYNC16(st_ + ATILEB + dA + dstep,      pBh + k0_ + rstep);      \
        CP_ASYNC16(st_ + ATILEB + BTILEB + dA,         pBl + k0_);          \
        CP_ASYNC16(st_ + ATILEB + BTILEB + dA + dstep, pBl + k0_ + rstep);  \
        CP_COMMIT();                                                        \
    } while (0)

    ISSUE(0);
    ISSUE(1);

    for (int c = 0; c < nch; c++) {
        if (c + 2 < nch) CP_WAIT1(); else CP_WAIT0();
        __syncthreads();
        if (c + 2 < nch) ISSUE(c + 2);

        const uint32_t tb  = sb + (c % 3) * STAGEB;
        const uint32_t aT  = tb;
        const uint32_t bHi = tb + ATILEB;
        const uint32_t bLo = tb + ATILEB + BTILEB;

#pragma unroll
        for (int ks = 0; ks < 2; ks++) {
            const uint32_t ksb = ks * 32;
            uint32_t af[4][4];
#pragma unroll
            for (int mt = 0; mt < 4; mt++)
                ldsm_x4(af[mt], aT + a_off + mt * (16 * LDT * 2) + ksb);
#pragma unroll
            for (int nt = 0; nt < 8; nt++) {
                uint32_t bh[2], bl[2];
                ldsm_x2(bh, bHi + b_off + nt * (8 * LDT * 2) + ksb);
                ldsm_x2(bl, bLo + b_off + nt * (8 * LDT * 2) + ksb);
#pragma unroll
                for (int mt = 0; mt < 4; mt++) {
                    mma_f16(acc[mt][nt], af[mt], bh);
                    mma_f16(acc[mt][nt], af[mt], bl);
                }
            }
        }
        __syncthreads();
    }
#undef ISSUE

#pragma unroll
    for (int mt = 0; mt < 4; mt++) {
        const int r = m0 + wm * 64 + mt * 16 + (lane >> 2);
#pragma unroll
        for (int nt = 0; nt < 8; nt++) {
            const int cc = n0 + wn * 64 + nt * 8 + (lane & 3) * 2;
            float2 v0 = {acc[mt][nt][0], acc[mt][nt][1]};
            float2 v1 = {acc[mt][nt][2], acc[mt][nt][3]};
            *(float2*)&C[(size_t)r * N + cc]       = v0;
            *(float2*)&C[(size_t)(r + 8) * N + cc] = v1;
        }
    }
}

// ---------------------------------------------------------------------------
// RMSNorm + RoPE (table-based). If olo == nullptr emit single fp16,
// else emit fp16 hi/lo split.
// ---------------------------------------------------------------------------
__global__ void __launch_bounds__(256)
rmsrope_h(const float* __restrict__ in, int rowstride,
          const float* __restrict__ w, int nheads,
          __half* __restrict__ ohi, __half* __restrict__ olo,
          const float2* __restrict__ cs)
{
    const int lane   = threadIdx.x & 31;
    const int warpid = threadIdx.x >> 5;
    const int row    = blockIdx.x * 8 + warpid;
    const int bt     = row / nheads;
    const int head   = row - bt * nheads;
    const int t      = bt & (T_ - 1);

    const float* p = in + (size_t)bt * rowstride + head * HD_;
    float2 x = *(const float2*)&p[2 * lane];

    float ss = x.x * x.x + x.y * x.y;
#pragma unroll
    for (int o = 16; o > 0; o >>= 1)
        ss += __shfl_xor_sync(0xffffffffu, ss, o);

    float rms = rsqrtf(ss * (1.0f / HD_) + 1e-6f);
    float xn1 = x.x * rms * w[2 * lane];
    float xn2 = x.y * rms * w[2 * lane + 1];

    float2 csv = cs[t * 32 + lane];
    float ox = xn1 * csv.x - xn2 * csv.y;
    float oy = xn2 * csv.x + xn1 * csv.y;

    const size_t idx = (size_t)bt * (nheads * HD_) + head * HD_ + 2 * lane;
    if (olo) {
        uint32_t hi, lo;
        packhl_h(ox, oy, hi, lo);
        *(uint32_t*)&ohi[idx] = hi;
        *(uint32_t*)&olo[idx] = lo;
    } else {
        *(uint32_t*)&ohi[idx] = pack_h2(ox, oy);
    }
}

// ---------------------------------------------------------------------------
// V convert + transpose: fp32 strided [bt, g*64] -> fp16 hi/lo [b,g,hd,T]
// ---------------------------------------------------------------------------
__global__ void __launch_bounds__(256)
vconv(const float* __restrict__ v, int rowstride,
      __half* __restrict__ vth, __half* __restrict__ vtl)
{
    __shared__ float s[64][65];
    const int t0 = blockIdx.x * 64;
    const int g  = blockIdx.y;
    const int b  = blockIdx.z;
    const int tid = threadIdx.x;

#pragma unroll
    for (int it = 0; it < 4; it++) {
        int tr = it * 16 + (tid >> 4);
        int c4 = (tid & 15) * 4;
        float4 val = *(const float4*)&v[(size_t)(b * T_ + t0 + tr) * rowstride
                                        + g * HD_ + c4];
        s[tr][c4 + 0] = val.x; s[tr][c4 + 1] = val.y;
        s[tr][c4 + 2] = val.z; s[tr][c4 + 3] = val.w;
    }
    __syncthreads();

    const int hd  = tid >> 2;
    const int seg = tid & 3;
    __half hi[16], lo[16];
#pragma unroll
    for (int j = 0; j < 16; j++) {
        float x = s[seg * 16 + j][hd];
        __half h = __float2half(x);
        hi[j] = h;
        lo[j] = __float2half(x - __half2float(h));
    }
    const size_t ob = ((size_t)(b * G_ + g) * HD_ + hd) * T_ + t0 + seg * 16;
    *(uint4*)&vth[ob]     = *(uint4*)&hi[0];
    *(uint4*)&vth[ob + 8] = *(uint4*)&hi[8];
    *(uint4*)&vtl[ob]     = *(uint4*)&lo[0];
    *(uint4*)&vtl[ob + 8] = *(uint4*)&lo[8];
}

// ---------------------------------------------------------------------------
// Causal GQA flash attention, HMMA fp16 2-pass.
// CTA = 128 q-rows, 4 warps (32 rows each), 64-key tiles.
// Q single fp16 (registers); K,V split hi/lo; P single fp16.
// ---------------------------------------------------------------------------
#define ASTR  72
#define ATILE (64 * ASTR * 2)
#define AQT   (128 * ASTR * 2)
#define ATT_SMEM (AQT + 4 * ATILE)        // 55296 B
#define SC_LOG2E 0.18033688011112042f

__global__ void __launch_bounds__(128)
attn_mma(const __half* __restrict__ q16,
         const __half* __restrict__ khi, const __half* __restrict__ klo,
         const __half* __restrict__ vth, const __half* __restrict__ vtl,
         __half* __restrict__ o16)
{
    extern __shared__ char smraw[];
    const uint32_t sb   = smem_u32(smraw);
    const uint32_t sQ   = sb;
    const uint32_t sKhi = sb + AQT;
    const uint32_t sKlo = sKhi + ATILE;
    const uint32_t sVhi = sKlo + ATILE;
    const uint32_t sVlo = sVhi + ATILE;

    const int tid  = threadIdx.x;
    const int lane = tid & 31;
    const int w    = tid >> 5;
    const int mblk = gridDim.x - 1 - blockIdx.x;
    const int m0   = mblk * 128;
    const int h    = blockIdx.y;
    const int b    = blockIdx.z;
    const int g    = h >> 2;

    // ---- stage Q tile (single fp16) ----
    {
        const __half* qp = q16 + ((size_t)(b * T_ + m0) * H_ + h) * HD_;
        const int r = tid >> 3;
        const int c = (tid & 7) * 8;
        const uint32_t soff = (uint32_t)(r * ASTR + c) * 2;
#pragma unroll
        for (int it = 0; it < 8; it++) {
            uint4 a = *(const uint4*)(qp + (size_t)(it * 16 + r) * (H_ * HD_) + c);
            STS128(sQ + it * 16 * ASTR * 2 + soff, a);
        }
    }
    __syncthreads();

    uint32_t qf[2][4][4];
#pragma unroll
    for (int mt = 0; mt < 2; mt++) {
        const uint32_t a_off = (uint32_t)((w * 32 + mt * 16 + (lane & 15)) * ASTR * 2
                                          + (lane >> 4) * 16);
#pragma unroll
        for (int ks = 0; ks < 4; ks++)
            ldsm_x4(qf[mt][ks], sQ + a_off + ks * 32);
    }

    float o[2][8][4];
#pragma unroll
    for (int mt = 0; mt < 2; mt++)
#pragma unroll
        for (int nt = 0; nt < 8; nt++)
#pragma unroll
            for (int e = 0; e < 4; e++) o[mt][nt][e] = 0.f;
    float mrow[2][2] = {{-INFINITY, -INFINITY}, {-INFINITY, -INFINITY}};
    float lrow[2][2] = {{0.f, 0.f}, {0.f, 0.f}};

    const __half* khb = khi + ((size_t)b * T_ * G_ + g) * HD_;
    const __half* klb = klo + ((size_t)b * T_ * G_ + g) * HD_;
    const __half* vhb = vth + (size_t)(b * G_ + g) * HD_ * T_;
    const __half* vlb = vtl + (size_t)(b * G_ + g) * HD_ * T_;

    for (int n0 = 0; n0 < m0 + 128; n0 += 64) {
        // ---- load K/V tiles ----
        {
            const int r = tid >> 3;
            const int c = (tid & 7) * 8;
            const uint32_t soff = (uint32_t)(r * ASTR + c) * 2;
#pragma unroll
            for (int it = 0; it < 4; it++) {
                const int rr = it * 16 + r;
                const uint32_t so = soff + it * 16 * ASTR * 2;
                uint4 a = *(const uint4*)(khb + (size_t)(n0 + rr) * (G_ * HD_) + c);
                STS128(sKhi + so, a);
                uint4 bb = *(const uint4*)(klb + (size_t)(n0 + rr) * (G_ * HD_) + c);
                STS128(sKlo + so, bb);
                uint4 cc = *(const uint4*)(vhb + (size_t)rr * T_ + n0 + c);
                STS128(sVhi + so, cc);
                uint4 dd = *(const uint4*)(vlb + (size_t)rr * T_ + n0 + c);
                STS128(sVlo + so, dd);
            }
        }
        __syncthreads();

        const bool skip = (n0 > m0 + w * 32 + 31);
        if (!skip) {
            const bool needm = (n0 + 63 > m0 + w * 32);

            // ---- S = Q16 (Khi + Klo)^T ----
            float s[2][8][4];
#pragma unroll
            for (int mt = 0; mt < 2; mt++)
#pragma unroll
                for (int nt = 0; nt < 8; nt++)
#pragma unroll
                    for (int e = 0; e < 4; e++) s[mt][nt][e] = 0.f;

#pragma unroll
            for (int ks = 0; ks < 4; ks++) {
#pragma unroll
                for (int nt = 0; nt < 8; nt++) {
                    const uint32_t bo = (uint32_t)((nt * 8 + (lane & 7)) * ASTR * 2
                                                   + ((lane >> 3) & 1) * 16) + ks * 32;
                    uint32_t bh[2], bl[2];
                    ldsm_x2(bh, sKhi + bo);
                    ldsm_x2(bl, sKlo + bo);
#pragma unroll
                    for (int mt = 0; mt < 2; mt++) {
                        mma_f16(s[mt][nt], qf[mt][ks], bh);
                        mma_f16(s[mt][nt], qf[mt][ks], bl);
                    }
                }
            }

            // ---- per-group softmax; s dies into single-fp16 P fragments ----
            uint32_t ap[2][4][4];
#pragma unroll
            for (int mt = 0; mt < 2; mt++) {
                const int grow0 = m0 + w * 32 + mt * 16 + (lane >> 2);
                const int grow1 = grow0 + 8;
                float mx0 = -INFINITY, mx1 = -INFINITY;
#pragma unroll
                for (int nt = 0; nt < 8; nt++) {
                    const int col = n0 + nt * 8 + (lane & 3) * 2;
#pragma unroll
                    for (int e = 0; e < 2; e++) {
                        float v = s[mt][nt][e] * SC_LOG2E;
                        if (needm && (col + e > grow0)) v = -1e30f;
                        s[mt][nt][e] = v;
                        mx0 = fmaxf(mx0, v);
                    }
#pragma unroll
                    for (int e = 2; e < 4; e++) {
                        float v = s[mt][nt][e] * SC_LOG2E;
                        if (needm && (col + e - 2 > grow1)) v = -1e30f;
                        s[mt][nt][e] = v;
                        mx1 = fmaxf(mx1, v);
                    }
                }
                mx0 = fmaxf(mx0, __shfl_xor_sync(0xffffffffu, mx0, 1));
                mx0 = fmaxf(mx0, __shfl_xor_sync(0xffffffffu, mx0, 2));
                mx1 = fmaxf(mx1, __shfl_xor_sync(0xffffffffu, mx1, 1));
                mx1 = fmaxf(mx1, __shfl_xor_sync(0xffffffffu, mx1, 2));

                const float mn0 = fmaxf(mrow[mt][0], mx0);
                const float mn1 = fmaxf(mrow[mt][1], mx1);
                const float c0 = ex2(mrow[mt][0] - mn0);
                const float c1 = ex2(mrow[mt][1] - mn1);
                mrow[mt][0] = mn0; mrow[mt][1] = mn1;

                float s0 = 0.f, s1 = 0.f;
#pragma unroll
                for (int nt = 0; nt < 8; nt++) {
                    float p0 = ex2(s[mt][nt][0] - mn0);
                    float p1 = ex2(s[mt][nt][1] - mn0);
                    float p2 = ex2(s[mt][nt][2] - mn1);
                    float p3 = ex2(s[mt][nt][3] - mn1);
                    s[mt][nt][0] = p0; s[mt][nt][1] = p1;
                    s[mt][nt][2] = p2; s[mt][nt][3] = p3;
                    s0 += p0 + p1; s1 += p2 + p3;
                }
                s0 += __shfl_xor_sync(0xffffffffu, s0, 1);
                s0 += __shfl_xor_sync(0xffffffffu, s0, 2);
                s1 += __shfl_xor_sync(0xffffffffu, s1, 1);
                s1 += __shfl_xor_sync(0xffffffffu, s1, 2);
                lrow[mt][0] = lrow[mt][0] * c0 + s0;
                lrow[mt][1] = lrow[mt][1] * c1 + s1;

#pragma unroll
                for (int nt = 0; nt < 8; nt++) {
                    o[mt][nt][0] *= c0; o[mt][nt][1] *= c0;
                    o[mt][nt][2] *= c1; o[mt][nt][3] *= c1;
                }
#pragma unroll
                for (int ks = 0; ks < 4; ks++) {
                    ap[mt][ks][0] = pack_h2(s[mt][2 * ks][0],     s[mt][2 * ks][1]);
                    ap[mt][ks][1] = pack_h2(s[mt][2 * ks][2],     s[mt][2 * ks][3]);
                    ap[mt][ks][2] = pack_h2(s[mt][2 * ks + 1][0], s[mt][2 * ks + 1][1]);
                    ap[mt][ks][3] = pack_h2(s[mt][2 * ks + 1][2], s[mt][2 * ks + 1][3]);
                }
            }

            // ---- O += P16 (Vhi + Vlo) ----
#pragma unroll
            for (int nt = 0; nt < 8; nt++) {
#pragma unroll
                for (int ks = 0; ks < 4; ks++) {
                    const uint32_t bo = (uint32_t)((nt * 8 + (lane & 7)) * ASTR * 2
                                                   + ((lane >> 3) & 1) * 16) + ks * 32;
                    uint32_t vh[2], vl[2];
                    ldsm_x2(vh, sVhi + bo);
                    ldsm_x2(vl, sVlo + bo);
#pragma unroll
                    for (int mt = 0; mt < 2; mt++) {
                        mma_f16(o[mt][nt], ap[mt][ks], vh);
                        mma_f16(o[mt][nt], ap[mt][ks], vl);
                    }
                }
            }
        }
        __syncthreads();
    }

    // ---- epilogue: normalize, emit single fp16 ----
#pragma unroll
    for (int mt = 0; mt < 2; mt++) {
        const float i0 = 1.f / lrow[mt][0];
        const float i1 = 1.f / lrow[mt][1];
        const int grow = m0 + w * 32 + mt * 16 + (lane >> 2);
        const size_t base0 = (size_t)(b * T_ + grow) * D_ + h * HD_ + (lane & 3) * 2;
        const size_t base1 = base0 + 8 * D_;
#pragma unroll
        for (int nt = 0; nt < 8; nt++) {
            *(uint32_t*)&o16[base0 + nt * 8] =
                pack_h2(o[mt][nt][0] * i0, o[mt][nt][1] * i0);
            *(uint32_t*)&o16[base1 + nt * 8] =
                pack_h2(o[mt][nt][2] * i1, o[mt][nt][3] * i1);
        }
    }
}

// ---------------------------------------------------------------------------
// Launch
// ---------------------------------------------------------------------------
extern "C" void kernel_launch(void* const* d_in, const int* in_sizes, int n_in,
                              void* d_out, int out_size)
{
    const float* x    = (const float*)d_in[0];
    const float* Wq   = (const float*)d_in[1];
    const float* Wk   = (const float*)d_in[2];
    const float* Wv   = (const float*)d_in[3];
    const float* Wo   = (const float*)d_in[4];
    const float* qn_w = (const float*)d_in[5];
    const float* kn_w = (const float*)d_in[6];
    float* out = (float*)d_out;

    float *qp, *kvp;
    float2* cs;
    __half *x16, *wqhi, *wqlo, *wkvhi, *wkvlo, *wohi, *wolo;
    __half *q16, *khi, *klo, *vthi, *vtlo, *o16;
    cudaGetSymbolAddress((void**)&qp, g_q);
    cudaGetSymbolAddress((void**)&kvp, g_kv);
    cudaGetSymbolAddress((void**)&cs, g_cs);
    cudaGetSymbolAddress((void**)&x16, g_x16);
    cudaGetSymbolAddress((void**)&wqhi, g_wqhi);
    cudaGetSymbolAddress((void**)&wqlo, g_wqlo);
    cudaGetSymbolAddress((void**)&wkvhi, g_wkvhi);
    cudaGetSymbolAddress((void**)&wkvlo, g_wkvlo);
    cudaGetSymbolAddress((void**)&wohi, g_wohi);
    cudaGetSymbolAddress((void**)&wolo, g_wolo);
    cudaGetSymbolAddress((void**)&q16, g_q16);
    cudaGetSymbolAddress((void**)&khi, g_khi);
    cudaGetSymbolAddress((void**)&klo, g_klo);
    cudaGetSymbolAddress((void**)&vthi, g_vthi);
    cudaGetSymbolAddress((void**)&vtlo, g_vtlo);
    cudaGetSymbolAddress((void**)&o16, g_o16);

    cudaFuncSetAttribute(gemm_h2,
                         cudaFuncAttributeMaxDynamicSharedMemorySize, GEMM_SMEM);
    cudaFuncSetAttribute(attn_mma,
                         cudaFuncAttributeMaxDynamicSharedMemorySize, ATT_SMEM);

    // --- preconversion + rope table ---
    f2h_single<<<(BT_ * D_ / 4 + 255) / 256, 256>>>(x, x16, BT_ * D_ / 4);
    f2h_split<<<(D_ * D_ / 4 + 255) / 256, 256>>>(Wq, wqhi, wqlo, D_ * D_ / 4);
    f2h_split<<<(256 * D_ / 4 + 255) / 256, 256>>>(Wk, wkvhi, wkvlo, 256 * D_ / 4);
    f2h_split<<<(256 * D_ / 4 + 255) / 256, 256>>>(Wv, wkvhi + 256 * D_,
                                                   wkvlo + 256 * D_, 256 * D_ / 4);
    f2h_split<<<(D_ * D_ / 4 + 255) / 256, 256>>>(Wo, wohi, wolo, D_ * D_ / 4);
    rope_table<<<T_, 32>>>(cs);

    // --- projections: q and fused k|v ---
    gemm_h2<<<dim3(D_ / 128, BT_ / 256), 256, GEMM_SMEM>>>(
        x16, wqhi, wqlo, qp, BT_, D_, D_);
    gemm_h2<<<dim3(KVW / 128, BT_ / 256), 256, GEMM_SMEM>>>(
        x16, wkvhi, wkvlo, kvp, BT_, KVW, D_);

    // --- RMSNorm + RoPE; V convert+transpose ---
    rmsrope_h<<<(BT_ * H_) / 8, 256>>>(qp, D_, qn_w, H_, q16, nullptr, cs);
    rmsrope_h<<<(BT_ * G_) / 8, 256>>>(kvp, KVW, kn_w, G_, khi, klo, cs);
    vconv<<<dim3(T_ / 64, G_, B_), 256>>>(kvp + 256, KVW, vthi, vtlo);

    // --- causal GQA flash attention ---
    attn_mma<<<dim3(T_ / 128, H_, B_), 128, ATT_SMEM>>>(
        q16, khi, klo, vthi, vtlo, o16);

    // --- output projection ---
    gemm_h2<<<dim3(D_ / 128, BT_ / 256), 256, GEMM_SMEM>>>(
        o16, wohi, wolo, out, BT_, D_, D_);
}

// round 8
// speedup vs baseline: 1.5637x; 1.0245x over previous
#include <cuda_runtime.h>
#include <cuda_fp16.h>
#include <math.h>
#include <stdint.h>

// ---------------------------------------------------------------------------
// Problem constants
// ---------------------------------------------------------------------------
#define B_   4
#define T_   2048
#define D_   1024
#define H_   16
#define G_   4
#define HD_  64
#define BT_  (B_ * T_)          // 8192
#define KVW  512                 // fused K|V projection width

// ---------------------------------------------------------------------------
// Scratch (device globals -- no allocation allowed)
// ---------------------------------------------------------------------------
__device__ float g_q[BT_ * D_];
__device__ float g_kv[BT_ * KVW];
__device__ float2 g_cs[T_ * 32];

__device__ __half g_x16[BT_ * D_];
__device__ __half g_wqhi[D_ * D_],  g_wqlo[D_ * D_];
__device__ __half g_wkvhi[KVW * D_], g_wkvlo[KVW * D_];
__device__ __half g_wohi[D_ * D_],  g_wolo[D_ * D_];
__device__ __half g_q16[BT_ * D_];
__device__ __half g_khi[BT_ * G_ * HD_], g_klo[BT_ * G_ * HD_];
__device__ __half g_vthi[B_ * G_ * HD_ * T_], g_vtlo[B_ * G_ * HD_ * T_];
__device__ __half g_o16[BT_ * D_];

// ---------------------------------------------------------------------------
// PTX helpers (base sm_100-legal)
// ---------------------------------------------------------------------------
__device__ __forceinline__ uint32_t smem_u32(const void* p) {
    uint32_t a;
    asm("{ .reg .u64 t; cvta.to.shared.u64 t, %1; cvt.u32.u64 %0, t; }"
        : "=r"(a) : "l"(p));
    return a;
}
__device__ __forceinline__ void ldsm_x4(uint32_t (&r)[4], uint32_t addr) {
    asm volatile("ldmatrix.sync.aligned.m8n8.x4.shared.b16 {%0,%1,%2,%3}, [%4];"
                 : "=r"(r[0]), "=r"(r[1]), "=r"(r[2]), "=r"(r[3]) : "r"(addr));
}
__device__ __forceinline__ void mma_f16(float (&d)[4], const uint32_t (&a)[4],
                                        uint32_t b0, uint32_t b1) {
    asm volatile(
        "mma.sync.aligned.m16n8k16.row.col.f32.f16.f16.f32 "
        "{%0,%1,%2,%3}, {%4,%5,%6,%7}, {%8,%9}, {%0,%1,%2,%3};"
        : "+f"(d[0]), "+f"(d[1]), "+f"(d[2]), "+f"(d[3])
        : "r"(a[0]), "r"(a[1]), "r"(a[2]), "r"(a[3]), "r"(b0), "r"(b1));
}
__device__ __forceinline__ float ex2(float x) {
    float y;
    asm("ex2.approx.ftz.f32 %0, %1;" : "=f"(y) : "f"(x));
    return y;
}
__device__ __forceinline__ uint32_t pack_h2(float x, float y) {
    __half2 h = __floats2half2_rn(x, y);
    return *(uint32_t*)&h;
}
__device__ __forceinline__ void packhl_h(float x, float y,
                                         uint32_t& hi, uint32_t& lo) {
    __half2 h = __floats2half2_rn(x, y);
    float lx = x - __half2float(__low2half(h));
    float ly = y - __half2float(__high2half(h));
    __half2 l = __floats2half2_rn(lx, ly);
    hi = *(uint32_t*)&h; lo = *(uint32_t*)&l;
}
#define STS128(addr, v) \
    asm volatile("st.shared.v4.b32 [%0], {%1,%2,%3,%4};" \
                 :: "r"(addr), "r"((v).x), "r"((v).y), "r"((v).z), "r"((v).w))
#define CP_ASYNC16(dst, src) \
    asm volatile("cp.async.cg.shared.global [%0], [%1], 16;" \
                 :: "r"(dst), "l"(src))
#define CP_COMMIT() asm volatile("cp.async.commit_group;" ::: "memory")
#define CP_WAIT1()  asm volatile("cp.async.wait_group 1;" ::: "memory")
#define CP_WAIT0()  asm volatile("cp.async.wait_group 0;" ::: "memory")

// ---------------------------------------------------------------------------
// Converters + rope table
// ---------------------------------------------------------------------------
__global__ void __launch_bounds__(256)
f2h_single(const float* __restrict__ in, __half* __restrict__ out, int n4)
{
    const int i = blockIdx.x * 256 + threadIdx.x;
    if (i >= n4) return;
    float4 v = ((const float4*)in)[i];
    uint2 o = {pack_h2(v.x, v.y), pack_h2(v.z, v.w)};
    ((uint2*)out)[i] = o;
}

__global__ void __launch_bounds__(256)
f2h_split(const float* __restrict__ in, __half* __restrict__ hi,
          __half* __restrict__ lo, int n4)
{
    const int i = blockIdx.x * 256 + threadIdx.x;
    if (i >= n4) return;
    float4 v = ((const float4*)in)[i];
    uint32_t h0, h1, l0, l1;
    packhl_h(v.x, v.y, h0, l0);
    packhl_h(v.z, v.w, h1, l1);
    uint2 ho = {h0, h1}, lv = {l0, l1};
    ((uint2*)hi)[i] = ho;
    ((uint2*)lo)[i] = lv;
}

__global__ void rope_table(float2* __restrict__ cs)
{
    const int t = blockIdx.x;
    const int l = threadIdx.x;
    double inv_freq = pow(10000.0, -(double)l / 32.0);
    double ang = (double)t * inv_freq;
    cs[t * 32 + l] = make_float2((float)cos(ang), (float)sin(ang));
}

// ---------------------------------------------------------------------------
// Tensor-core GEMM (HMMA fp16, 2-pass): C[M,N] = A16[M,K] @ (Bhi+Blo)[N,K]^T.
// CTA 256x128, 8 warps, warp tile 64x64, KC=32, 3-stage cp.async pipeline,
// single __syncthreads per chunk, B-fragments via paired ldsm_x4.
// ---------------------------------------------------------------------------
#define KC      32
#define LDT     40
#define ATILEB  (256 * LDT * 2)
#define BTILEB  (128 * LDT * 2)
#define STAGEB  (ATILEB + 2 * BTILEB)
#define GEMM_SMEM (3 * STAGEB)

__global__ void __launch_bounds__(256, 1)
gemm_h2(const __half* __restrict__ A16,
        const __half* __restrict__ Bhi, const __half* __restrict__ Blo,
        float* __restrict__ C, int M, int N, int K)
{
    extern __shared__ char smraw[];
    const uint32_t sb = smem_u32(smraw);

    const int tid  = threadIdx.x;
    const int lane = tid & 31;
    const int wid  = tid >> 5;
    const int wm   = wid & 3;
    const int wn   = wid >> 2;
    const int m0 = blockIdx.y * 256;
    const int n0 = blockIdx.x * 128;

    const int r0   = tid >> 2;
    const int cseg = (tid & 3) * 8;
    const __half* pA = A16 + (size_t)(m0 + r0) * K + cseg;
    const __half* pBh = Bhi + (size_t)(n0 + r0) * K + cseg;
    const __half* pBl = Blo + (size_t)(n0 + r0) * K + cseg;
    const uint32_t dA = (uint32_t)(r0 * LDT + cseg) * 2;
    const size_t rstep = (size_t)64 * K;
    const uint32_t dstep = 64 * LDT * 2;

    const uint32_t a_off = (uint32_t)(((wm * 64 + (lane & 15)) * LDT
                                       + (lane >> 4) * 8) * 2);
    // paired-B x4 addressing: mats {ntp rows 0..7 k0, k16, rows 8..15 k0, k16}
    const uint32_t b4_off = (uint32_t)(((wn * 64 + (lane & 7)
                                         + ((lane >> 4) & 1) * 8) * LDT) * 2
                                       + ((lane >> 3) & 1) * 16);

    float acc[4][8][4];
#pragma unroll
    for (int i = 0; i < 4; i++)
#pragma unroll
        for (int j = 0; j < 8; j++)
#pragma unroll
            for (int e = 0; e < 4; e++) acc[i][j][e] = 0.f;

    const int nch = K / KC;

#define ISSUE(c) do {                                                       \
        const uint32_t st_ = sb + ((c) % 3) * STAGEB;                       \
        const size_t k0_ = (size_t)(c) * KC;                                \
        CP_ASYNC16(st_ + dA,               pA + k0_);                       \
        CP_ASYNC16(st_ + dA + dstep,       pA + k0_ + rstep);               \
        CP_ASYNC16(st_ + dA + 2 * dstep,   pA + k0_ + 2 * rstep);           \
        CP_ASYNC16(st_ + dA + 3 * dstep,   pA + k0_ + 3 * rstep);           \
        CP_ASYNC16(st_ + ATILEB + dA,              pBh + k0_);              \
        CP_ASYNC16(st_ + ATILEB + dA + dstep,      pBh + k0_ + rstep);      \
        CP_ASYNC16(st_ + ATILEB + BTILEB + dA,         pBl + k0_);          \
        CP_ASYNC16(st_ + ATILEB + BTILEB + dA + dstep, pBl + k0_ + rstep);  \
        CP_COMMIT();                                                        \
    } while (0)

    ISSUE(0);
    ISSUE(1);

    for (int c = 0; c < nch; c++) {
        if (c + 2 < nch) CP_WAIT1(); else CP_WAIT0();
        __syncthreads();
        if (c + 2 < nch) ISSUE(c + 2);

        const uint32_t tb  = sb + (c % 3) * STAGEB;
        const uint32_t aT  = tb;
        const uint32_t bHi = tb + ATILEB;
        const uint32_t bLo = tb + ATILEB + BTILEB;

#pragma unroll
        for (int ks = 0; ks < 2; ks++) {
            const uint32_t ksb = ks * 32;
            uint32_t af[4][4];
#pragma unroll
            for (int mt = 0; mt < 4; mt++)
                ldsm_x4(af[mt], aT + a_off + mt * (16 * LDT * 2) + ksb);
#pragma unroll
            for (int ntp = 0; ntp < 4; ntp++) {
                uint32_t bh[4], bl[4];
                ldsm_x4(bh, bHi + b4_off + ntp * (16 * LDT * 2) + ksb);
                ldsm_x4(bl, bLo + b4_off + ntp * (16 * LDT * 2) + ksb);
#pragma unroll
                for (int mt = 0; mt < 4; mt++) {
                    mma_f16(acc[mt][2 * ntp],     af[mt], bh[0], bh[1]);
                    mma_f16(acc[mt][2 * ntp],     af[mt], bl[0], bl[1]);
                    mma_f16(acc[mt][2 * ntp + 1], af[mt], bh[2], bh[3]);
                    mma_f16(acc[mt][2 * ntp + 1], af[mt], bl[2], bl[3]);
                }
            }
        }
        // no trailing sync: top-of-loop sync orders reads vs ISSUE overwrite
    }
#undef ISSUE

#pragma unroll
    for (int mt = 0; mt < 4; mt++) {
        const int r = m0 + wm * 64 + mt * 16 + (lane >> 2);
#pragma unroll
        for (int nt = 0; nt < 8; nt++) {
            const int cc = n0 + wn * 64 + nt * 8 + (lane & 3) * 2;
            float2 v0 = {acc[mt][nt][0], acc[mt][nt][1]};
            float2 v1 = {acc[mt][nt][2], acc[mt][nt][3]};
            *(float2*)&C[(size_t)r * N + cc]       = v0;
            *(float2*)&C[(size_t)(r + 8) * N + cc] = v1;
        }
    }
}

// ---------------------------------------------------------------------------
// RMSNorm + RoPE (table-based)
// ---------------------------------------------------------------------------
__global__ void __launch_bounds__(256)
rmsrope_h(const float* __restrict__ in, int rowstride,
          const float* __restrict__ w, int nheads,
          __half* __restrict__ ohi, __half* __restrict__ olo,
          const float2* __restrict__ cs)
{
    const int lane   = threadIdx.x & 31;
    const int warpid = threadIdx.x >> 5;
    const int row    = blockIdx.x * 8 + warpid;
    const int bt     = row / nheads;
    const int head   = row - bt * nheads;
    const int t      = bt & (T_ - 1);

    const float* p = in + (size_t)bt * rowstride + head * HD_;
    float2 x = *(const float2*)&p[2 * lane];

    float ss = x.x * x.x + x.y * x.y;
#pragma unroll
    for (int o = 16; o > 0; o >>= 1)
        ss += __shfl_xor_sync(0xffffffffu, ss, o);

    float rms = rsqrtf(ss * (1.0f / HD_) + 1e-6f);
    float xn1 = x.x * rms * w[2 * lane];
    float xn2 = x.y * rms * w[2 * lane + 1];

    float2 csv = cs[t * 32 + lane];
    float ox = xn1 * csv.x - xn2 * csv.y;
    float oy = xn2 * csv.x + xn1 * csv.y;

    const size_t idx = (size_t)bt * (nheads * HD_) + head * HD_ + 2 * lane;
    if (olo) {
        uint32_t hi, lo;
        packhl_h(ox, oy, hi, lo);
        *(uint32_t*)&ohi[idx] = hi;
        *(uint32_t*)&olo[idx] = lo;
    } else {
        *(uint32_t*)&ohi[idx] = pack_h2(ox, oy);
    }
}

// ---------------------------------------------------------------------------
// V convert + transpose: fp32 strided [bt, g*64] -> fp16 hi/lo [b,g,hd,T]
// ---------------------------------------------------------------------------
__global__ void __launch_bounds__(256)
vconv(const float* __restrict__ v, int rowstride,
      __half* __restrict__ vth, __half* __restrict__ vtl)
{
    __shared__ float s[64][65];
    const int t0 = blockIdx.x * 64;
    const int g  = blockIdx.y;
    const int b  = blockIdx.z;
    const int tid = threadIdx.x;

#pragma unroll
    for (int it = 0; it < 4; it++) {
        int tr = it * 16 + (tid >> 4);
        int c4 = (tid & 15) * 4;
        float4 val = *(const float4*)&v[(size_t)(b * T_ + t0 + tr) * rowstride
                                        + g * HD_ + c4];
        s[tr][c4 + 0] = val.x; s[tr][c4 + 1] = val.y;
        s[tr][c4 + 2] = val.z; s[tr][c4 + 3] = val.w;
    }
    __syncthreads();

    const int hd  = tid >> 2;
    const int seg = tid & 3;
    __half hi[16], lo[16];
#pragma unroll
    for (int j = 0; j < 16; j++) {
        float x = s[seg * 16 + j][hd];
        __half h = __float2half(x);
        hi[j] = h;
        lo[j] = __float2half(x - __half2float(h));
    }
    const size_t ob = ((size_t)(b * G_ + g) * HD_ + hd) * T_ + t0 + seg * 16;
    *(uint4*)&vth[ob]     = *(uint4*)&hi[0];
    *(uint4*)&vth[ob + 8] = *(uint4*)&hi[8];
    *(uint4*)&vtl[ob]     = *(uint4*)&lo[0];
    *(uint4*)&vtl[ob + 8] = *(uint4*)&lo[8];
}

// ---------------------------------------------------------------------------
// Causal GQA flash attention, HMMA fp16 2-pass.
// CTA = 128 q-rows, 4 warps (32 rows each), 64-key tiles.
// cp.async double-buffered K/V (issued one tile ahead), single sync/tile.
// ---------------------------------------------------------------------------
#define ASTR  72
#define ATILE (64 * ASTR * 2)            // 9216 B
#define AQT   (128 * ASTR * 2)           // 18432 B
#define KVSTG (4 * ATILE)                // 36864 B per stage
#define ATT_SMEM (AQT + 2 * KVSTG)       // 92160 B
#define SC_LOG2E 0.18033688011112042f

__global__ void __launch_bounds__(128)
attn_mma(const __half* __restrict__ q16,
         const __half* __restrict__ khi, const __half* __restrict__ klo,
         const __half* __restrict__ vth, const __half* __restrict__ vtl,
         __half* __restrict__ o16)
{
    extern __shared__ char smraw[];
    const uint32_t sb  = smem_u32(smraw);
    const uint32_t sQ  = sb;
    const uint32_t sKV = sb + AQT;

    const int tid  = threadIdx.x;
    const int lane = tid & 31;
    const int w    = tid >> 5;
    const int mblk = gridDim.x - 1 - blockIdx.x;
    const int m0   = mblk * 128;
    const int h    = blockIdx.y;
    const int b    = blockIdx.z;
    const int g    = h >> 2;

    const __half* khb = khi + ((size_t)b * T_ * G_ + g) * HD_;
    const __half* klb = klo + ((size_t)b * T_ * G_ + g) * HD_;
    const __half* vhb = vth + (size_t)(b * G_ + g) * HD_ * T_;
    const __half* vlb = vtl + (size_t)(b * G_ + g) * HD_ * T_;

    const int ntiles = (m0 + 128) / 64;

    // cp.async K/V issue: 4 arrays x 64 rows x 128B, 16B chunks
    const int ar = tid >> 3;             // 0..15
    const int ac = (tid & 7) * 8;        // half offset
#define AISSUE(n0_, stg_) do {                                               \
        const uint32_t st_ = sKV + (uint32_t)(stg_) * KVSTG;                 \
        _Pragma("unroll")                                                    \
        for (int it_ = 0; it_ < 4; it_++) {                                  \
            const int rr_ = it_ * 16 + ar;                                   \
            const uint32_t so_ = (uint32_t)(rr_ * ASTR + ac) * 2;            \
            CP_ASYNC16(st_ + so_,             khb + (size_t)((n0_) + rr_) * (G_ * HD_) + ac); \
            CP_ASYNC16(st_ + ATILE + so_,     klb + (size_t)((n0_) + rr_) * (G_ * HD_) + ac); \
            CP_ASYNC16(st_ + 2 * ATILE + so_, vhb + (size_t)rr_ * T_ + (n0_) + ac); \
            CP_ASYNC16(st_ + 3 * ATILE + so_, vlb + (size_t)rr_ * T_ + (n0_) + ac); \
        }                                                                    \
        CP_COMMIT();                                                         \
    } while (0)

    AISSUE(0, 0);

    // ---- stage Q tile (overlaps with first K/V load) ----
    {
        const __half* qp = q16 + ((size_t)(b * T_ + m0) * H_ + h) * HD_;
        const uint32_t soff = (uint32_t)(ar * ASTR + ac) * 2;
#pragma unroll
        for (int it = 0; it < 8; it++) {
            uint4 a = *(const uint4*)(qp + (size_t)(it * 16 + ar) * (H_ * HD_) + ac);
            STS128(sQ + it * 16 * ASTR * 2 + soff, a);
        }
    }
    __syncthreads();

    uint32_t qf[2][4][4];
#pragma unroll
    for (int mt = 0; mt < 2; mt++) {
        const uint32_t a_off = (uint32_t)((w * 32 + mt * 16 + (lane & 15)) * ASTR * 2
                                          + (lane >> 4) * 16);
#pragma unroll
        for (int ks = 0; ks < 4; ks++)
            ldsm_x4(qf[mt][ks], sQ + a_off + ks * 32);
    }

    float o[2][8][4];
#pragma unroll
    for (int mt = 0; mt < 2; mt++)
#pragma unroll
        for (int nt = 0; nt < 8; nt++)
#pragma unroll
            for (int e = 0; e < 4; e++) o[mt][nt][e] = 0.f;
    float mrow[2][2] = {{-INFINITY, -INFINITY}, {-INFINITY, -INFINITY}};
    float lrow[2][2] = {{0.f, 0.f}, {0.f, 0.f}};

    // paired-B x4 addressing within a 64-row tile
    const uint32_t b4_off = (uint32_t)((((lane & 7) + ((lane >> 4) & 1) * 8) * ASTR) * 2
                                       + ((lane >> 3) & 1) * 16);

    for (int t = 0; t < ntiles; t++) {
        CP_WAIT0();
        __syncthreads();
        if (t + 1 < ntiles) AISSUE((t + 1) * 64, (t + 1) & 1);

        const int n0 = t * 64;
        const uint32_t kvb  = sKV + (uint32_t)(t & 1) * KVSTG;
        const uint32_t sKhi = kvb;
        const uint32_t sKlo = kvb + ATILE;
        const uint32_t sVhi = kvb + 2 * ATILE;
        const uint32_t sVlo = kvb + 3 * ATILE;

        const bool skip = (n0 > m0 + w * 32 + 31);
        if (!skip) {
            const bool needm = (n0 + 63 > m0 + w * 32);

            // ---- S = Q16 (Khi + Klo)^T ----
            float s[2][8][4];
#pragma unroll
            for (int mt = 0; mt < 2; mt++)
#pragma unroll
                for (int nt = 0; nt < 8; nt++)
#pragma unroll
                    for (int e = 0; e < 4; e++) s[mt][nt][e] = 0.f;

#pragma unroll
            for (int ks = 0; ks < 4; ks++) {
#pragma unroll
                for (int ntp = 0; ntp < 4; ntp++) {
                    const uint32_t bo = b4_off + ntp * (16 * ASTR * 2) + ks * 32;
                    uint32_t bh[4], bl[4];
                    ldsm_x4(bh, sKhi + bo);
                    ldsm_x4(bl, sKlo + bo);
#pragma unroll
                    for (int mt = 0; mt < 2; mt++) {
                        mma_f16(s[mt][2 * ntp],     qf[mt][ks], bh[0], bh[1]);
                        mma_f16(s[mt][2 * ntp],     qf[mt][ks], bl[0], bl[1]);
                        mma_f16(s[mt][2 * ntp + 1], qf[mt][ks], bh[2], bh[3]);
                        mma_f16(s[mt][2 * ntp + 1], qf[mt][ks], bl[2], bl[3]);
                    }
                }
            }

            // ---- per-group softmax; s dies into single-fp16 P fragments ----
            uint32_t ap[2][4][4];
#pragma unroll
            for (int mt = 0; mt < 2; mt++) {
                const int grow0 = m0 + w * 32 + mt * 16 + (lane >> 2);
                const int grow1 = grow0 + 8;
                float mx0 = -INFINITY, mx1 = -INFINITY;
#pragma unroll
                for (int nt = 0; nt < 8; nt++) {
                    const int col = n0 + nt * 8 + (lane & 3) * 2;
#pragma unroll
                    for (int e = 0; e < 2; e++) {
                        float v = s[mt][nt][e] * SC_LOG2E;
                        if (needm && (col + e > grow0)) v = -1e30f;
                        s[mt][nt][e] = v;
                        mx0 = fmaxf(mx0, v);
                    }
#pragma unroll
                    for (int e = 2; e < 4; e++) {
                        float v = s[mt][nt][e] * SC_LOG2E;
                        if (needm && (col + e - 2 > grow1)) v = -1e30f;
                        s[mt][nt][e] = v;
                        mx1 = fmaxf(mx1, v);
                    }
                }
                mx0 = fmaxf(mx0, __shfl_xor_sync(0xffffffffu, mx0, 1));
                mx0 = fmaxf(mx0, __shfl_xor_sync(0xffffffffu, mx0, 2));
                mx1 = fmaxf(mx1, __shfl_xor_sync(0xffffffffu, mx1, 1));
                mx1 = fmaxf(mx1, __shfl_xor_sync(0xffffffffu, mx1, 2));

                const float mn0 = fmaxf(mrow[mt][0], mx0);
                const float mn1 = fmaxf(mrow[mt][1], mx1);
                const float c0 = ex2(mrow[mt][0] - mn0);
                const float c1 = ex2(mrow[mt][1] - mn1);
                mrow[mt][0] = mn0; mrow[mt][1] = mn1;

                float s0 = 0.f, s1 = 0.f;
#pragma unroll
                for (int nt = 0; nt < 8; nt++) {
                    float p0 = ex2(s[mt][nt][0] - mn0);
                    float p1 = ex2(s[mt][nt][1] - mn0);
                    float p2 = ex2(s[mt][nt][2] - mn1);
                    float p3 = ex2(s[mt][nt][3] - mn1);
                    s[mt][nt][0] = p0; s[mt][nt][1] = p1;
                    s[mt][nt][2] = p2; s[mt][nt][3] = p3;
                    s0 += p0 + p1; s1 += p2 + p3;
                }
                s0 += __shfl_xor_sync(0xffffffffu, s0, 1);
                s0 += __shfl_xor_sync(0xffffffffu, s0, 2);
                s1 += __shfl_xor_sync(0xffffffffu, s1, 1);
                s1 += __shfl_xor_sync(0xffffffffu, s1, 2);
                lrow[mt][0] = lrow[mt][0] * c0 + s0;
                lrow[mt][1] = lrow[mt][1] * c1 + s1;

#pragma unroll
                for (int nt = 0; nt < 8; nt++) {
                    o[mt][nt][0] *= c0; o[mt][nt][1] *= c0;
                    o[mt][nt][2] *= c1; o[mt][nt][3] *= c1;
                }
#pragma unroll
                for (int ks = 0; ks < 4; ks++) {
                    ap[mt][ks][0] = pack_h2(s[mt][2 * ks][0],     s[mt][2 * ks][1]);
                    ap[mt][ks][1] = pack_h2(s[mt][2 * ks][2],     s[mt][2 * ks][3]);
                    ap[mt][ks][2] = pack_h2(s[mt][2 * ks + 1][0], s[mt][2 * ks + 1][1]);
                    ap[mt][ks][3] = pack_h2(s[mt][2 * ks + 1][2], s[mt][2 * ks + 1][3]);
                }
            }

            // ---- O += P16 (Vhi + Vlo) ----
#pragma unroll
            for (int ntp = 0; ntp < 4; ntp++) {
#pragma unroll
                for (int ks = 0; ks < 4; ks++) {
                    const uint32_t bo = b4_off + ntp * (16 * ASTR * 2) + ks * 32;
                    uint32_t vh[4], vl[4];
                    ldsm_x4(vh, sVhi + bo);
                    ldsm_x4(vl, sVlo + bo);
#pragma unroll
                    for (int mt = 0; mt < 2; mt++) {
                        mma_f16(o[mt][2 * ntp],     ap[mt][ks], vh[0], vh[1]);
                        mma_f16(o[mt][2 * ntp],     ap[mt][ks], vl[0], vl[1]);
                        mma_f16(o[mt][2 * ntp + 1], ap[mt][ks], vh[2], vh[3]);
                        mma_f16(o[mt][2 * ntp + 1], ap[mt][ks], vl[2], vl[3]);
                    }
                }
            }
        }
        // no trailing sync: next iteration's top sync orders reads vs AISSUE
    }
#undef AISSUE

    // ---- epilogue: normalize, emit single fp16 ----
#pragma unroll
    for (int mt = 0; mt < 2; mt++) {
        const float i0 = 1.f / lrow[mt][0];
        const float i1 = 1.f / lrow[mt][1];
        const int grow = m0 + w * 32 + mt * 16 + (lane >> 2);
        const size_t base0 = (size_t)(b * T_ + grow) * D_ + h * HD_ + (lane & 3) * 2;
        const size_t base1 = base0 + 8 * D_;
#pragma unroll
        for (int nt = 0; nt < 8; nt++) {
            *(uint32_t*)&o16[base0 + nt * 8] =
                pack_h2(o[mt][nt][0] * i0, o[mt][nt][1] * i0);
            *(uint32_t*)&o16[base1 + nt * 8] =
                pack_h2(o[mt][nt][2] * i1, o[mt][nt][3] * i1);
        }
    }
}

// ---------------------------------------------------------------------------
// Launch
// ---------------------------------------------------------------------------
extern "C" void kernel_launch(void* const* d_in, const int* in_sizes, int n_in,
                              void* d_out, int out_size)
{
    const float* x    = (const float*)d_in[0];
    const float* Wq   = (const float*)d_in[1];
    const float* Wk   = (const float*)d_in[2];
    const float* Wv   = (const float*)d_in[3];
    const float* Wo   = (const float*)d_in[4];
    const float* qn_w = (const float*)d_in[5];
    const float* kn_w = (const float*)d_in[6];
    float* out = (float*)d_out;

    float *qp, *kvp;
    float2* cs;
    __half *x16, *wqhi, *wqlo, *wkvhi, *wkvlo, *wohi, *wolo;
    __half *q16, *khi, *klo, *vthi, *vtlo, *o16;
    cudaGetSymbolAddress((void**)&qp, g_q);
    cudaGetSymbolAddress((void**)&kvp, g_kv);
    cudaGetSymbolAddress((void**)&cs, g_cs);
    cudaGetSymbolAddress((void**)&x16, g_x16);
    cudaGetSymbolAddress((void**)&wqhi, g_wqhi);
    cudaGetSymbolAddress((void**)&wqlo, g_wqlo);
    cudaGetSymbolAddress((void**)&wkvhi, g_wkvhi);
    cudaGetSymbolAddress((void**)&wkvlo, g_wkvlo);
    cudaGetSymbolAddress((void**)&wohi, g_wohi);
    cudaGetSymbolAddress((void**)&wolo, g_wolo);
    cudaGetSymbolAddress((void**)&q16, g_q16);
    cudaGetSymbolAddress((void**)&khi, g_khi);
    cudaGetSymbolAddress((void**)&klo, g_klo);
    cudaGetSymbolAddress((void**)&vthi, g_vthi);
    cudaGetSymbolAddress((void**)&vtlo, g_vtlo);
    cudaGetSymbolAddress((void**)&o16, g_o16);

    cudaFuncSetAttribute(gemm_h2,
                         cudaFuncAttributeMaxDynamicSharedMemorySize, GEMM_SMEM);
    cudaFuncSetAttribute(attn_mma,
                         cudaFuncAttributeMaxDynamicSharedMemorySize, ATT_SMEM);

    // --- preconversion + rope table ---
    f2h_single<<<(BT_ * D_ / 4 + 255) / 256, 256>>>(x, x16, BT_ * D_ / 4);
    f2h_split<<<(D_ * D_ / 4 + 255) / 256, 256>>>(Wq, wqhi, wqlo, D_ * D_ / 4);
    f2h_split<<<(256 * D_ / 4 + 255) / 256, 256>>>(Wk, wkvhi, wkvlo, 256 * D_ / 4);
    f2h_split<<<(256 * D_ / 4 + 255) / 256, 256>>>(Wv, wkvhi + 256 * D_,
                                                   wkvlo + 256 * D_, 256 * D_ / 4);
    f2h_split<<<(D_ * D_ / 4 + 255) / 256, 256>>>(Wo, wohi, wolo, D_ * D_ / 4);
    rope_table<<<T_, 32>>>(cs);

    // --- projections: q and fused k|v ---
    gemm_h2<<<dim3(D_ / 128, BT_ / 256), 256, GEMM_SMEM>>>(
        x16, wqhi, wqlo, qp, BT_, D_, D_);
    gemm_h2<<<dim3(KVW / 128, BT_ / 256), 256, GEMM_SMEM>>>(
        x16, wkvhi, wkvlo, kvp, BT_, KVW, D_);

    // --- RMSNorm + RoPE; V convert+transpose ---
    rmsrope_h<<<(BT_ * H_) / 8, 256>>>(qp, D_, qn_w, H_, q16, nullptr, cs);
    rmsrope_h<<<(BT_ * G_) / 8, 256>>>(kvp, KVW, kn_w, G_, khi, klo, cs);
    vconv<<<dim3(T_ / 64, G_, B_), 256>>>(kvp + 256, KVW, vthi, vtlo);

    // --- causal GQA flash attention (cp.async double-buffered) ---
    attn_mma<<<dim3(T_ / 128, H_, B_), 128, ATT_SMEM>>>(
        q16, khi, klo, vthi, vtlo, o16);

    // --- output projection ---
    gemm_h2<<<dim3(D_ / 128, BT_ / 256), 256, GEMM_SMEM>>>(
        o16, wohi, wolo, out, BT_, D_, D_);
}

// round 10
// speedup vs baseline: 1.5910x; 1.0175x over previous
#include <cuda_runtime.h>
#include <cuda_fp16.h>
#include <math.h>
#include <stdint.h>

// ---------------------------------------------------------------------------
// Problem constants
// ---------------------------------------------------------------------------
#define B_   4
#define T_   2048
#define D_   1024
#define H_   16
#define G_   4
#define HD_  64
#define BT_  (B_ * T_)          // 8192
#define KVW  512                 // fused K|V projection width

// ---------------------------------------------------------------------------
// Scratch (device globals -- no allocation allowed)
// ---------------------------------------------------------------------------
__device__ float g_q[BT_ * D_];
__device__ float g_kv[BT_ * KVW];
__device__ float2 g_cs[T_ * 32];

__device__ __half g_x16[BT_ * D_];
__device__ __half g_wqhi[D_ * D_],  g_wqlo[D_ * D_];
__device__ __half g_wkvhi[KVW * D_], g_wkvlo[KVW * D_];
__device__ __half g_wohi[D_ * D_],  g_wolo[D_ * D_];
__device__ __half g_q16[BT_ * D_];
__device__ __half g_khi[BT_ * G_ * HD_], g_klo[BT_ * G_ * HD_];
__device__ __half g_vthi[B_ * G_ * HD_ * T_], g_vtlo[B_ * G_ * HD_ * T_];
__device__ __half g_o16[BT_ * D_];

// ---------------------------------------------------------------------------
// PTX helpers (base sm_100-legal)
// ---------------------------------------------------------------------------
__device__ __forceinline__ uint32_t smem_u32(const void* p) {
    uint32_t a;
    asm("{ .reg .u64 t; cvta.to.shared.u64 t, %1; cvt.u32.u64 %0, t; }"
        : "=r"(a) : "l"(p));
    return a;
}
__device__ __forceinline__ void ldsm_x4(uint32_t (&r)[4], uint32_t addr) {
    asm volatile("ldmatrix.sync.aligned.m8n8.x4.shared.b16 {%0,%1,%2,%3}, [%4];"
                 : "=r"(r[0]), "=r"(r[1]), "=r"(r[2]), "=r"(r[3]) : "r"(addr));
}
__device__ __forceinline__ void mma_f16(float (&d)[4], const uint32_t (&a)[4],
                                        uint32_t b0, uint32_t b1) {
    asm volatile(
        "mma.sync.aligned.m16n8k16.row.col.f32.f16.f16.f32 "
        "{%0,%1,%2,%3}, {%4,%5,%6,%7}, {%8,%9}, {%0,%1,%2,%3};"
        : "+f"(d[0]), "+f"(d[1]), "+f"(d[2]), "+f"(d[3])
        : "r"(a[0]), "r"(a[1]), "r"(a[2]), "r"(a[3]), "r"(b0), "r"(b1));
}
__device__ __forceinline__ float ex2(float x) {
    float y;
    asm("ex2.approx.ftz.f32 %0, %1;" : "=f"(y) : "f"(x));
    return y;
}
__device__ __forceinline__ uint32_t pack_h2(float x, float y) {
    __half2 h = __floats2half2_rn(x, y);
    return *(uint32_t*)&h;
}
__device__ __forceinline__ void packhl_h(float x, float y,
                                         uint32_t& hi, uint32_t& lo) {
    __half2 h = __floats2half2_rn(x, y);
    float lx = x - __half2float(__low2half(h));
    float ly = y - __half2float(__high2half(h));
    __half2 l = __floats2half2_rn(lx, ly);
    hi = *(uint32_t*)&h; lo = *(uint32_t*)&l;
}
#define STS128(addr, v) \
    asm volatile("st.shared.v4.b32 [%0], {%1,%2,%3,%4};" \
                 :: "r"(addr), "r"((v).x), "r"((v).y), "r"((v).z), "r"((v).w))
#define CP_ASYNC16(dst, src) \
    asm volatile("cp.async.cg.shared.global [%0], [%1], 16;" \
                 :: "r"(dst), "l"(src))
#define CP_COMMIT() asm volatile("cp.async.commit_group;" ::: "memory")
#define CP_WAIT1()  asm volatile("cp.async.wait_group 1;" ::: "memory")
#define CP_WAIT0()  asm volatile("cp.async.wait_group 0;" ::: "memory")

// ---------------------------------------------------------------------------
// Fused prologue: x->fp16, W splits, rope table. One launch.
// ---------------------------------------------------------------------------
#define NB_X   8192
#define NB_WQ  1024
#define NB_WK  256
#define NB_WV  256
#define NB_WO  1024
#define NB_CS  256
#define NB_TOT (NB_X + NB_WQ + NB_WK + NB_WV + NB_WO + NB_CS)

__global__ void __launch_bounds__(256)
prep(const float* __restrict__ x,  const float* __restrict__ Wq,
     const float* __restrict__ Wk, const float* __restrict__ Wv,
     const float* __restrict__ Wo,
     __half* __restrict__ x16,
     __half* __restrict__ wqhi,  __half* __restrict__ wqlo,
     __half* __restrict__ wkvhi, __half* __restrict__ wkvlo,
     __half* __restrict__ wohi,  __half* __restrict__ wolo,
     float2* __restrict__ cs)
{
    const int bid = blockIdx.x;
    const int tid = threadIdx.x;

    if (bid < NB_X) {                       // x -> single fp16
        const int i = bid * 256 + tid;
        float4 v = ((const float4*)x)[i];
        uint2 o = {pack_h2(v.x, v.y), pack_h2(v.z, v.w)};
        ((uint2*)x16)[i] = o;
        return;
    }
    const float* src; __half* hi; __half* lo; int i;
    if (bid < NB_X + NB_WQ) {
        i = (bid - NB_X) * 256 + tid;
        src = Wq; hi = wqhi; lo = wqlo;
    } else if (bid < NB_X + NB_WQ + NB_WK) {
        i = (bid - NB_X - NB_WQ) * 256 + tid;
        src = Wk; hi = wkvhi; lo = wkvlo;
    } else if (bid < NB_X + NB_WQ + NB_WK + NB_WV) {
        i = (bid - NB_X - NB_WQ - NB_WK) * 256 + tid;
        src = Wv; hi = wkvhi + 256 * D_; lo = wkvlo + 256 * D_;
    } else if (bid < NB_X + NB_WQ + NB_WK + NB_WV + NB_WO) {
        i = (bid - NB_X - NB_WQ - NB_WK - NB_WV) * 256 + tid;
        src = Wo; hi = wohi; lo = wolo;
    } else {                                // rope table
        const int idx = (bid - (NB_TOT - NB_CS)) * 256 + tid;
        const int t = idx >> 5, l = idx & 31;
        double inv_freq = pow(10000.0, -(double)l / 32.0);
        double ang = (double)t * inv_freq;
        cs[idx] = make_float2((float)cos(ang), (float)sin(ang));
        return;
    }
    float4 v = ((const float4*)src)[i];
    uint32_t h0, h1, l0, l1;
    packhl_h(v.x, v.y, h0, l0);
    packhl_h(v.z, v.w, h1, l1);
    uint2 ho = {h0, h1}, lv = {l0, l1};
    ((uint2*)hi)[i] = ho;
    ((uint2*)lo)[i] = lv;
}

// ---------------------------------------------------------------------------
// Tensor-core GEMM (HMMA fp16, 2-pass): C[M,N] = A16[M,K] @ (Bhi+Blo)[N,K]^T.
// CTA 128x128, 8 warps, warp tile 64x32 (wm 0..1, wn 0..3), KC=32,
// 3-stage cp.async, 2 CTAs/SM (16 warps/SM).
// Load mapping: r0 = tid>>2 (64 rows), cseg = (tid&3)*8 (full 32-half rows),
// second chunk at +64 rows -> full 128x32 coverage per array.
// ---------------------------------------------------------------------------
#define KC      32
#define LDT     40
#define ATILEB  (128 * LDT * 2)           // 10240 B
#define BTILEB  (128 * LDT * 2)           // 10240 B
#define STAGEB  (ATILEB + 2 * BTILEB)     // 30720 B
#define GEMM_SMEM (3 * STAGEB)            // 92160 B

__global__ void __launch_bounds__(256, 2)
gemm_h2(const __half* __restrict__ A16,
        const __half* __restrict__ Bhi, const __half* __restrict__ Blo,
        float* __restrict__ C, int M, int N, int K)
{
    extern __shared__ char smraw[];
    const uint32_t sb = smem_u32(smraw);

    const int tid  = threadIdx.x;
    const int lane = tid & 31;
    const int wid  = tid >> 5;
    const int wm   = wid & 1;             // 0..1 -> 64 rows each
    const int wn   = wid >> 1;            // 0..3 -> 32 cols each
    const int m0 = blockIdx.y * 128;
    const int n0 = blockIdx.x * 128;

    const int r0   = tid >> 2;            // 0..63
    const int cseg = (tid & 3) * 8;       // 0,8,16,24 (halves)
    const __half* pA  = A16 + (size_t)(m0 + r0) * K + cseg;
    const __half* pBh = Bhi + (size_t)(n0 + r0) * K + cseg;
    const __half* pBl = Blo + (size_t)(n0 + r0) * K + cseg;
    const uint32_t dA = (uint32_t)(r0 * LDT + cseg) * 2;
    const size_t rstep = (size_t)64 * K;
    const uint32_t dstep = 64 * LDT * 2;

    const uint32_t a_off = (uint32_t)(((wm * 64 + (lane & 15)) * LDT
                                       + (lane >> 4) * 8) * 2);
    const uint32_t b4_off = (uint32_t)(((wn * 32 + (lane & 7)
                                         + ((lane >> 4) & 1) * 8) * LDT) * 2
                                       + ((lane >> 3) & 1) * 16);

    float acc[4][4][4];
#pragma unroll
    for (int i = 0; i < 4; i++)
#pragma unroll
        for (int j = 0; j < 4; j++)
#pragma unroll
            for (int e = 0; e < 4; e++) acc[i][j][e] = 0.f;

    const int nch = K / KC;

#define ISSUE(c) do {                                                       \
        const uint32_t st_ = sb + ((c) % 3) * STAGEB;                       \
        const size_t k0_ = (size_t)(c) * KC;                                \
        CP_ASYNC16(st_ + dA,                            pA + k0_);          \
        CP_ASYNC16(st_ + dA + dstep,                    pA + k0_ + rstep);  \
        CP_ASYNC16(st_ + ATILEB + dA,                   pBh + k0_);         \
        CP_ASYNC16(st_ + ATILEB + dA + dstep,           pBh + k0_ + rstep); \
        CP_ASYNC16(st_ + ATILEB + BTILEB + dA,          pBl + k0_);         \
        CP_ASYNC16(st_ + ATILEB + BTILEB + dA + dstep,  pBl + k0_ + rstep); \
        CP_COMMIT();                                                        \
    } while (0)

    ISSUE(0);
    ISSUE(1);

    for (int c = 0; c < nch; c++) {
        if (c + 2 < nch) CP_WAIT1(); else CP_WAIT0();
        __syncthreads();
        if (c + 2 < nch) ISSUE(c + 2);

        const uint32_t tb  = sb + (c % 3) * STAGEB;
        const uint32_t aT  = tb;
        const uint32_t bHi = tb + ATILEB;
        const uint32_t bLo = tb + ATILEB + BTILEB;

#pragma unroll
        for (int ks = 0; ks < 2; ks++) {
            const uint32_t ksb = ks * 32;
            uint32_t af[4][4];
#pragma unroll
            for (int mt = 0; mt < 4; mt++)
                ldsm_x4(af[mt], aT + a_off + mt * (16 * LDT * 2) + ksb);
#pragma unroll
            for (int ntp = 0; ntp < 2; ntp++) {
                uint32_t bh[4], bl[4];
                ldsm_x4(bh, bHi + b4_off + ntp * (16 * LDT * 2) + ksb);
                ldsm_x4(bl, bLo + b4_off + ntp * (16 * LDT * 2) + ksb);
#pragma unroll
                for (int mt = 0; mt < 4; mt++) {
                    mma_f16(acc[mt][2 * ntp],     af[mt], bh[0], bh[1]);
                    mma_f16(acc[mt][2 * ntp],     af[mt], bl[0], bl[1]);
                    mma_f16(acc[mt][2 * ntp + 1], af[mt], bh[2], bh[3]);
                    mma_f16(acc[mt][2 * ntp + 1], af[mt], bl[2], bl[3]);
                }
            }
        }
    }
#undef ISSUE

#pragma unroll
    for (int mt = 0; mt < 4; mt++) {
        const int r = m0 + wm * 64 + mt * 16 + (lane >> 2);
#pragma unroll
        for (int nt = 0; nt < 4; nt++) {
            const int cc = n0 + wn * 32 + nt * 8 + (lane & 3) * 2;
            float2 v0 = {acc[mt][nt][0], acc[mt][nt][1]};
            float2 v1 = {acc[mt][nt][2], acc[mt][nt][3]};
            *(float2*)&C[(size_t)r * N + cc]       = v0;
            *(float2*)&C[(size_t)(r + 8) * N + cc] = v1;
        }
    }
}

// ---------------------------------------------------------------------------
// RMSNorm + RoPE (table-based)
// ---------------------------------------------------------------------------
__global__ void __launch_bounds__(256)
rmsrope_h(const float* __restrict__ in, int rowstride,
          const float* __restrict__ w, int nheads,
          __half* __restrict__ ohi, __half* __restrict__ olo,
          const float2* __restrict__ cs)
{
    const int lane   = threadIdx.x & 31;
    const int warpid = threadIdx.x >> 5;
    const int row    = blockIdx.x * 8 + warpid;
    const int bt     = row / nheads;
    const int head   = row - bt * nheads;
    const int t      = bt & (T_ - 1);

    const float* p = in + (size_t)bt * rowstride + head * HD_;
    float2 x = *(const float2*)&p[2 * lane];

    float ss = x.x * x.x + x.y * x.y;
#pragma unroll
    for (int o = 16; o > 0; o >>= 1)
        ss += __shfl_xor_sync(0xffffffffu, ss, o);

    float rms = rsqrtf(ss * (1.0f / HD_) + 1e-6f);
    float xn1 = x.x * rms * w[2 * lane];
    float xn2 = x.y * rms * w[2 * lane + 1];

    float2 csv = cs[t * 32 + lane];
    float ox = xn1 * csv.x - xn2 * csv.y;
    float oy = xn2 * csv.x + xn1 * csv.y;

    const size_t idx = (size_t)bt * (nheads * HD_) + head * HD_ + 2 * lane;
    if (olo) {
        uint32_t hi, lo;
        packhl_h(ox, oy, hi, lo);
        *(uint32_t*)&ohi[idx] = hi;
        *(uint32_t*)&olo[idx] = lo;
    } else {
        *(uint32_t*)&ohi[idx] = pack_h2(ox, oy);
    }
}

// ---------------------------------------------------------------------------
// V convert + transpose: fp32 strided [bt, g*64] -> fp16 hi/lo [b,g,hd,T]
// ---------------------------------------------------------------------------
__global__ void __launch_bounds__(256)
vconv(const float* __restrict__ v, int rowstride,
      __half* __restrict__ vth, __half* __restrict__ vtl)
{
    __shared__ float s[64][65];
    const int t0 = blockIdx.x * 64;
    const int g  = blockIdx.y;
    const int b  = blockIdx.z;
    const int tid = threadIdx.x;

#pragma unroll
    for (int it = 0; it < 4; it++) {
        int tr = it * 16 + (tid >> 4);
        int c4 = (tid & 15) * 4;
        float4 val = *(const float4*)&v[(size_t)(b * T_ + t0 + tr) * rowstride
                                        + g * HD_ + c4];
        s[tr][c4 + 0] = val.x; s[tr][c4 + 1] = val.y;
        s[tr][c4 + 2] = val.z; s[tr][c4 + 3] = val.w;
    }
    __syncthreads();

    const int hd  = tid >> 2;
    const int seg = tid & 3;
    __half hi[16], lo[16];
#pragma unroll
    for (int j = 0; j < 16; j++) {
        float x = s[seg * 16 + j][hd];
        __half h = __float2half(x);
        hi[j] = h;
        lo[j] = __float2half(x - __half2float(h));
    }
    const size_t ob = ((size_t)(b * G_ + g) * HD_ + hd) * T_ + t0 + seg * 16;
    *(uint4*)&vth[ob]     = *(uint4*)&hi[0];
    *(uint4*)&vth[ob + 8] = *(uint4*)&hi[8];
    *(uint4*)&vtl[ob]     = *(uint4*)&lo[0];
    *(uint4*)&vtl[ob + 8] = *(uint4*)&lo[8];
}

// ---------------------------------------------------------------------------
// Causal GQA flash attention, HMMA fp16 2-pass (unchanged from round 8).
// ---------------------------------------------------------------------------
#define ASTR  72
#define ATILE (64 * ASTR * 2)            // 9216 B
#define AQT   (128 * ASTR * 2)           // 18432 B
#define KVSTG (4 * ATILE)                // 36864 B per stage
#define ATT_SMEM (AQT + 2 * KVSTG)       // 92160 B
#define SC_LOG2E 0.18033688011112042f

__global__ void __launch_bounds__(128)
attn_mma(const __half* __restrict__ q16,
         const __half* __restrict__ khi, const __half* __restrict__ klo,
         const __half* __restrict__ vth, const __half* __restrict__ vtl,
         __half* __restrict__ o16)
{
    extern __shared__ char smraw[];
    const uint32_t sb  = smem_u32(smraw);
    const uint32_t sQ  = sb;
    const uint32_t sKV = sb + AQT;

    const int tid  = threadIdx.x;
    const int lane = tid & 31;
    const int w    = tid >> 5;
    const int mblk = gridDim.x - 1 - blockIdx.x;
    const int m0   = mblk * 128;
    const int h    = blockIdx.y;
    const int b    = blockIdx.z;
    const int g    = h >> 2;

    const __half* khb = khi + ((size_t)b * T_ * G_ + g) * HD_;
    const __half* klb = klo + ((size_t)b * T_ * G_ + g) * HD_;
    const __half* vhb = vth + (size_t)(b * G_ + g) * HD_ * T_;
    const __half* vlb = vtl + (size_t)(b * G_ + g) * HD_ * T_;

    const int ntiles = (m0 + 128) / 64;

    const int ar = tid >> 3;             // 0..15
    const int ac = (tid & 7) * 8;
#define AISSUE(n0_, stg_) do {                                               \
        const uint32_t st_ = sKV + (uint32_t)(stg_) * KVSTG;                 \
        _Pragma("unroll")                                                    \
        for (int it_ = 0; it_ < 4; it_++) {                                  \
            const int rr_ = it_ * 16 + ar;                                   \
            const uint32_t so_ = (uint32_t)(rr_ * ASTR + ac) * 2;            \
            CP_ASYNC16(st_ + so_,             khb + (size_t)((n0_) + rr_) * (G_ * HD_) + ac); \
            CP_ASYNC16(st_ + ATILE + so_,     klb + (size_t)((n0_) + rr_) * (G_ * HD_) + ac); \
            CP_ASYNC16(st_ + 2 * ATILE + so_, vhb + (size_t)rr_ * T_ + (n0_) + ac); \
            CP_ASYNC16(st_ + 3 * ATILE + so_, vlb + (size_t)rr_ * T_ + (n0_) + ac); \
        }                                                                    \
        CP_COMMIT();                                                         \
    } while (0)

    AISSUE(0, 0);

    {
        const __half* qp = q16 + ((size_t)(b * T_ + m0) * H_ + h) * HD_;
        const uint32_t soff = (uint32_t)(ar * ASTR + ac) * 2;
#pragma unroll
        for (int it = 0; it < 8; it++) {
            uint4 a = *(const uint4*)(qp + (size_t)(it * 16 + ar) * (H_ * HD_) + ac);
            STS128(sQ + it * 16 * ASTR * 2 + soff, a);
        }
    }
    __syncthreads();

    uint32_t qf[2][4][4];
#pragma unroll
    for (int mt = 0; mt < 2; mt++) {
        const uint32_t a_off = (uint32_t)((w * 32 + mt * 16 + (lane & 15)) * ASTR * 2
                                          + (lane >> 4) * 16);
#pragma unroll
        for (int ks = 0; ks < 4; ks++)
            ldsm_x4(qf[mt][ks], sQ + a_off + ks * 32);
    }

    float o[2][8][4];
#pragma unroll
    for (int mt = 0; mt < 2; mt++)
#pragma unroll
        for (int nt = 0; nt < 8; nt++)
#pragma unroll
            for (int e = 0; e < 4; e++) o[mt][nt][e] = 0.f;
    float mrow[2][2] = {{-INFINITY, -INFINITY}, {-INFINITY, -INFINITY}};
    float lrow[2][2] = {{0.f, 0.f}, {0.f, 0.f}};

    const uint32_t b4_off = (uint32_t)((((lane & 7) + ((lane >> 4) & 1) * 8) * ASTR) * 2
                                       + ((lane >> 3) & 1) * 16);

    for (int t = 0; t < ntiles; t++) {
        CP_WAIT0();
        __syncthreads();
        if (t + 1 < ntiles) AISSUE((t + 1) * 64, (t + 1) & 1);

        const int n0 = t * 64;
        const uint32_t kvb  = sKV + (uint32_t)(t & 1) * KVSTG;
        const uint32_t sKhi = kvb;
        const uint32_t sKlo = kvb + ATILE;
        const uint32_t sVhi = kvb + 2 * ATILE;
        const uint32_t sVlo = kvb + 3 * ATILE;

        const bool skip = (n0 > m0 + w * 32 + 31);
        if (!skip) {
            const bool needm = (n0 + 63 > m0 + w * 32);

            float s[2][8][4];
#pragma unroll
            for (int mt = 0; mt < 2; mt++)
#pragma unroll
                for (int nt = 0; nt < 8; nt++)
#pragma unroll
                    for (int e = 0; e < 4; e++) s[mt][nt][e] = 0.f;

#pragma unroll
            for (int ks = 0; ks < 4; ks++) {
#pragma unroll
                for (int ntp = 0; ntp < 4; ntp++) {
                    const uint32_t bo = b4_off + ntp * (16 * ASTR * 2) + ks * 32;
                    uint32_t bh[4], bl[4];
                    ldsm_x4(bh, sKhi + bo);
                    ldsm_x4(bl, sKlo + bo);
#pragma unroll
                    for (int mt = 0; mt < 2; mt++) {
                        mma_f16(s[mt][2 * ntp],     qf[mt][ks], bh[0], bh[1]);
                        mma_f16(s[mt][2 * ntp],     qf[mt][ks], bl[0], bl[1]);
                        mma_f16(s[mt][2 * ntp + 1], qf[mt][ks], bh[2], bh[3]);
                        mma_f16(s[mt][2 * ntp + 1], qf[mt][ks], bl[2], bl[3]);
                    }
                }
            }

            uint32_t ap[2][4][4];
#pragma unroll
            for (int mt = 0; mt < 2; mt++) {
                const int grow0 = m0 + w * 32 + mt * 16 + (lane >> 2);
                const int grow1 = grow0 + 8;
                float mx0 = -INFINITY, mx1 = -INFINITY;
#pragma unroll
                for (int nt = 0; nt < 8; nt++) {
                    const int col = n0 + nt * 8 + (lane & 3) * 2;
#pragma unroll
                    for (int e = 0; e < 2; e++) {
                        float v = s[mt][nt][e] * SC_LOG2E;
                        if (needm && (col + e > grow0)) v = -1e30f;
                        s[mt][nt][e] = v;
                        mx0 = fmaxf(mx0, v);
                    }
#pragma unroll
                    for (int e = 2; e < 4; e++) {
                        float v = s[mt][nt][e] * SC_LOG2E;
                        if (needm && (col + e - 2 > grow1)) v = -1e30f;
                        s[mt][nt][e] = v;
                        mx1 = fmaxf(mx1, v);
                    }
                }
                mx0 = fmaxf(mx0, __shfl_xor_sync(0xffffffffu, mx0, 1));
                mx0 = fmaxf(mx0, __shfl_xor_sync(0xffffffffu, mx0, 2));
                mx1 = fmaxf(mx1, __shfl_xor_sync(0xffffffffu, mx1, 1));
                mx1 = fmaxf(mx1, __shfl_xor_sync(0xffffffffu, mx1, 2));

                const float mn0 = fmaxf(mrow[mt][0], mx0);
                const float mn1 = fmaxf(mrow[mt][1], mx1);
                const float c0 = ex2(mrow[mt][0] - mn0);
                const float c1 = ex2(mrow[mt][1] - mn1);
                mrow[mt][0] = mn0; mrow[mt][1] = mn1;

                float s0 = 0.f, s1 = 0.f;
#pragma unroll
                for (int nt = 0; nt < 8; nt++) {
                    float p0 = ex2(s[mt][nt][0] - mn0);
                    float p1 = ex2(s[mt][nt][1] - mn0);
                    float p2 = ex2(s[mt][nt][2] - mn1);
                    float p3 = ex2(s[mt][nt][3] - mn1);
                    s[mt][nt][0] = p0; s[mt][nt][1] = p1;
                    s[mt][nt][2] = p2; s[mt][nt][3] = p3;
                    s0 += p0 + p1; s1 += p2 + p3;
                }
                s0 += __shfl_xor_sync(0xffffffffu, s0, 1);
                s0 += __shfl_xor_sync(0xffffffffu, s0, 2);
                s1 += __shfl_xor_sync(0xffffffffu, s1, 1);
                s1 += __shfl_xor_sync(0xffffffffu, s1, 2);
                lrow[mt][0] = lrow[mt][0] * c0 + s0;
                lrow[mt][1] = lrow[mt][1] * c1 + s1;

#pragma unroll
                for (int nt = 0; nt < 8; nt++) {
                    o[mt][nt][0] *= c0; o[mt][nt][1] *= c0;
                    o[mt][nt][2] *= c1; o[mt][nt][3] *= c1;
                }
#pragma unroll
                for (int ks = 0; ks < 4; ks++) {
                    ap[mt][ks][0] = pack_h2(s[mt][2 * ks][0],     s[mt][2 * ks][1]);
                    ap[mt][ks][1] = pack_h2(s[mt][2 * ks][2],     s[mt][2 * ks][3]);
                    ap[mt][ks][2] = pack_h2(s[mt][2 * ks + 1][0], s[mt][2 * ks + 1][1]);
                    ap[mt][ks][3] = pack_h2(s[mt][2 * ks + 1][2], s[mt][2 * ks + 1][3]);
                }
            }

#pragma unroll
            for (int ntp = 0; ntp < 4; ntp++) {
#pragma unroll
                for (int ks = 0; ks < 4; ks++) {
                    const uint32_t bo = b4_off + ntp * (16 * ASTR * 2) + ks * 32;
                    uint32_t vh[4], vl[4];
                    ldsm_x4(vh, sVhi + bo);
                    ldsm_x4(vl, sVlo + bo);
#pragma unroll
                    for (int mt = 0; mt < 2; mt++) {
                        mma_f16(o[mt][2 * ntp],     ap[mt][ks], vh[0], vh[1]);
                        mma_f16(o[mt][2 * ntp],     ap[mt][ks], vl[0], vl[1]);
                        mma_f16(o[mt][2 * ntp + 1], ap[mt][ks], vh[2], vh[3]);
                        mma_f16(o[mt][2 * ntp + 1], ap[mt][ks], vl[2], vl[3]);
                    }
                }
            }
        }
    }
#undef AISSUE

#pragma unroll
    for (int mt = 0; mt < 2; mt++) {
        const float i0 = 1.f / lrow[mt][0];
        const float i1 = 1.f / lrow[mt][1];
        const int grow = m0 + w * 32 + mt * 16 + (lane >> 2);
        const size_t base0 = (size_t)(b * T_ + grow) * D_ + h * HD_ + (lane & 3) * 2;
        const size_t base1 = base0 + 8 * D_;
#pragma unroll
        for (int nt = 0; nt < 8; nt++) {
            *(uint32_t*)&o16[base0 + nt * 8] =
                pack_h2(o[mt][nt][0] * i0, o[mt][nt][1] * i0);
            *(uint32_t*)&o16[base1 + nt * 8] =
                pack_h2(o[mt][nt][2] * i1, o[mt][nt][3] * i1);
        }
    }
}

// ---------------------------------------------------------------------------
// Launch
// ---------------------------------------------------------------------------
extern "C" void kernel_launch(void* const* d_in, const int* in_sizes, int n_in,
                              void* d_out, int out_size)
{
    const float* x    = (const float*)d_in[0];
    const float* Wq   = (const float*)d_in[1];
    const float* Wk   = (const float*)d_in[2];
    const float* Wv   = (const float*)d_in[3];
    const float* Wo   = (const float*)d_in[4];
    const float* qn_w = (const float*)d_in[5];
    const float* kn_w = (const float*)d_in[6];
    float* out = (float*)d_out;

    float *qp, *kvp;
    float2* cs;
    __half *x16, *wqhi, *wqlo, *wkvhi, *wkvlo, *wohi, *wolo;
    __half *q16, *khi, *klo, *vthi, *vtlo, *o16;
    cudaGetSymbolAddress((void**)&qp, g_q);
    cudaGetSymbolAddress((void**)&kvp, g_kv);
    cudaGetSymbolAddress((void**)&cs, g_cs);
    cudaGetSymbolAddress((void**)&x16, g_x16);
    cudaGetSymbolAddress((void**)&wqhi, g_wqhi);
    cudaGetSymbolAddress((void**)&wqlo, g_wqlo);
    cudaGetSymbolAddress((void**)&wkvhi, g_wkvhi);
    cudaGetSymbolAddress((void**)&wkvlo, g_wkvlo);
    cudaGetSymbolAddress((void**)&wohi, g_wohi);
    cudaGetSymbolAddress((void**)&wolo, g_wolo);
    cudaGetSymbolAddress((void**)&q16, g_q16);
    cudaGetSymbolAddress((void**)&khi, g_khi);
    cudaGetSymbolAddress((void**)&klo, g_klo);
    cudaGetSymbolAddress((void**)&vthi, g_vthi);
    cudaGetSymbolAddress((void**)&vtlo, g_vtlo);
    cudaGetSymbolAddress((void**)&o16, g_o16);

    cudaFuncSetAttribute(gemm_h2,
                         cudaFuncAttributeMaxDynamicSharedMemorySize, GEMM_SMEM);
    cudaFuncSetAttribute(attn_mma,
                         cudaFuncAttributeMaxDynamicSharedMemorySize, ATT_SMEM);

    // --- fused prologue (converts + rope table), one launch ---
    prep<<<NB_TOT, 256>>>(x, Wq, Wk, Wv, Wo, x16,
                          wqhi, wqlo, wkvhi, wkvlo, wohi, wolo, cs);

    // --- projections: q and fused k|v (CTA 128x128, 2 CTAs/SM) ---
    gemm_h2<<<dim3(D_ / 128, BT_ / 128), 256, GEMM_SMEM>>>(
        x16, wqhi, wqlo, qp, BT_, D_, D_);
    gemm_h2<<<dim3(KVW / 128, BT_ / 128), 256, GEMM_SMEM>>>(
        x16, wkvhi, wkvlo, kvp, BT_, KVW, D_);

    // --- RMSNorm + RoPE; V convert+transpose ---
    rmsrope_h<<<(BT_ * H_) / 8, 256>>>(qp, D_, qn_w, H_, q16, nullptr, cs);
    rmsrope_h<<<(BT_ * G_) / 8, 256>>>(kvp, KVW, kn_w, G_, khi, klo, cs);
    vconv<<<dim3(T_ / 64, G_, B_), 256>>>(kvp + 256, KVW, vthi, vtlo);

    // --- causal GQA flash attention ---
    attn_mma<<<dim3(T_ / 128, H_, B_), 128, ATT_SMEM>>>(
        q16, khi, klo, vthi, vtlo, o16);

    // --- output projection ---
    gemm_h2<<<dim3(D_ / 128, BT_ / 128), 256, GEMM_SMEM>>>(
        o16, wohi, wolo, out, BT_, D_, D_);
}

// round 11
// speedup vs baseline: 2.5161x; 1.5814x over previous
#include <cuda_runtime.h>
#include <cuda_fp16.h>
#include <math.h>
#include <stdint.h>

// ---------------------------------------------------------------------------
// Problem constants
// ---------------------------------------------------------------------------
#define B_   4
#define T_   2048
#define D_   1024
#define H_   16
#define G_   4
#define HD_  64
#define BT_  (B_ * T_)          // 8192
#define KVW  512                 // fused K|V projection width

// ---------------------------------------------------------------------------
// Scratch (device globals -- no allocation allowed)
// ---------------------------------------------------------------------------
__device__ float g_q[BT_ * D_];
__device__ float g_kv[BT_ * KVW];
__device__ float2 g_cs[T_ * 32];

__device__ __half g_x16[BT_ * D_];
__device__ __half g_wq16[D_ * D_];
__device__ __half g_wkv16[KVW * D_];
__device__ __half g_wo16[D_ * D_];
__device__ __half g_q16[BT_ * D_];
__device__ __half g_k16[BT_ * G_ * HD_];
__device__ __half g_vt16[B_ * G_ * HD_ * T_];
__device__ __half g_o16[BT_ * D_];

// ---------------------------------------------------------------------------
// PTX helpers (base sm_100-legal)
// ---------------------------------------------------------------------------
__device__ __forceinline__ uint32_t smem_u32(const void* p) {
    uint32_t a;
    asm("{ .reg .u64 t; cvta.to.shared.u64 t, %1; cvt.u32.u64 %0, t; }"
        : "=r"(a) : "l"(p));
    return a;
}
__device__ __forceinline__ void ldsm_x4(uint32_t (&r)[4], uint32_t addr) {
    asm volatile("ldmatrix.sync.aligned.m8n8.x4.shared.b16 {%0,%1,%2,%3}, [%4];"
                 : "=r"(r[0]), "=r"(r[1]), "=r"(r[2]), "=r"(r[3]) : "r"(addr));
}
__device__ __forceinline__ void mma_f16(float (&d)[4], const uint32_t (&a)[4],
                                        uint32_t b0, uint32_t b1) {
    asm volatile(
        "mma.sync.aligned.m16n8k16.row.col.f32.f16.f16.f32 "
        "{%0,%1,%2,%3}, {%4,%5,%6,%7}, {%8,%9}, {%0,%1,%2,%3};"
        : "+f"(d[0]), "+f"(d[1]), "+f"(d[2]), "+f"(d[3])
        : "r"(a[0]), "r"(a[1]), "r"(a[2]), "r"(a[3]), "r"(b0), "r"(b1));
}
__device__ __forceinline__ float ex2(float x) {
    float y;
    asm("ex2.approx.ftz.f32 %0, %1;" : "=f"(y) : "f"(x));
    return y;
}
__device__ __forceinline__ uint32_t pack_h2(float x, float y) {
    __half2 h = __floats2half2_rn(x, y);
    return *(uint32_t*)&h;
}
#define STS128(addr, v) \
    asm volatile("st.shared.v4.b32 [%0], {%1,%2,%3,%4};" \
                 :: "r"(addr), "r"((v).x), "r"((v).y), "r"((v).z), "r"((v).w))
#define CP_ASYNC16(dst, src) \
    asm volatile("cp.async.cg.shared.global [%0], [%1], 16;" \
                 :: "r"(dst), "l"(src))
#define CP_COMMIT() asm volatile("cp.async.commit_group;" ::: "memory")
#define CP_WAIT1()  asm volatile("cp.async.wait_group 1;" ::: "memory")
#define CP_WAIT0()  asm volatile("cp.async.wait_group 0;" ::: "memory")

// ---------------------------------------------------------------------------
// Fused prologue: x->fp16, W->fp16, rope table. One launch.
// ---------------------------------------------------------------------------
#define NB_X   8192
#define NB_WQ  1024
#define NB_WK  256
#define NB_WV  256
#define NB_WO  1024
#define NB_CS  256
#define NB_TOT (NB_X + NB_WQ + NB_WK + NB_WV + NB_WO + NB_CS)

__global__ void __launch_bounds__(256)
prep(const float* __restrict__ x,  const float* __restrict__ Wq,
     const float* __restrict__ Wk, const float* __restrict__ Wv,
     const float* __restrict__ Wo,
     __half* __restrict__ x16,  __half* __restrict__ wq16,
     __half* __restrict__ wkv16, __half* __restrict__ wo16,
     float2* __restrict__ cs)
{
    const int bid = blockIdx.x;
    const int tid = threadIdx.x;

    const float* src; __half* dst; int i;
    if (bid < NB_X) {
        i = bid * 256 + tid; src = x; dst = x16;
    } else if (bid < NB_X + NB_WQ) {
        i = (bid - NB_X) * 256 + tid; src = Wq; dst = wq16;
    } else if (bid < NB_X + NB_WQ + NB_WK) {
        i = (bid - NB_X - NB_WQ) * 256 + tid; src = Wk; dst = wkv16;
    } else if (bid < NB_X + NB_WQ + NB_WK + NB_WV) {
        i = (bid - NB_X - NB_WQ - NB_WK) * 256 + tid;
        src = Wv; dst = wkv16 + 256 * D_;
    } else if (bid < NB_X + NB_WQ + NB_WK + NB_WV + NB_WO) {
        i = (bid - NB_X - NB_WQ - NB_WK - NB_WV) * 256 + tid;
        src = Wo; dst = wo16;
    } else {
        const int idx = (bid - (NB_TOT - NB_CS)) * 256 + tid;
        const int t = idx >> 5, l = idx & 31;
        double inv_freq = pow(10000.0, -(double)l / 32.0);
        double ang = (double)t * inv_freq;
        cs[idx] = make_float2((float)cos(ang), (float)sin(ang));
        return;
    }
    float4 v = ((const float4*)src)[i];
    uint2 o = {pack_h2(v.x, v.y), pack_h2(v.z, v.w)};
    ((uint2*)dst)[i] = o;
}

// ---------------------------------------------------------------------------
// Tensor-core GEMM (HMMA fp16, single pass): C[M,N] = A16[M,K] @ B16[N,K]^T.
// CTA 128x128, 8 warps, warp tile 64x32, KC=32, 3-stage cp.async, 2 CTAs/SM.
// ---------------------------------------------------------------------------
#define KC      32
#define LDT     40
#define ATILEB  (128 * LDT * 2)           // 10240 B
#define BTILEB  (128 * LDT * 2)           // 10240 B
#define STAGEB  (ATILEB + BTILEB)         // 20480 B
#define GEMM_SMEM (3 * STAGEB)            // 61440 B

__global__ void __launch_bounds__(256, 2)
gemm_h1(const __half* __restrict__ A16, const __half* __restrict__ B16,
        float* __restrict__ C, int M, int N, int K)
{
    extern __shared__ char smraw[];
    const uint32_t sb = smem_u32(smraw);

    const int tid  = threadIdx.x;
    const int lane = tid & 31;
    const int wid  = tid >> 5;
    const int wm   = wid & 1;             // 0..1 -> 64 rows each
    const int wn   = wid >> 1;            // 0..3 -> 32 cols each
    const int m0 = blockIdx.y * 128;
    const int n0 = blockIdx.x * 128;

    const int r0   = tid >> 2;            // 0..63
    const int cseg = (tid & 3) * 8;       // 0,8,16,24 (halves)
    const __half* pA = A16 + (size_t)(m0 + r0) * K + cseg;
    const __half* pB = B16 + (size_t)(n0 + r0) * K + cseg;
    const uint32_t dA = (uint32_t)(r0 * LDT + cseg) * 2;
    const size_t rstep = (size_t)64 * K;
    const uint32_t dstep = 64 * LDT * 2;

    const uint32_t a_off = (uint32_t)(((wm * 64 + (lane & 15)) * LDT
                                       + (lane >> 4) * 8) * 2);
    const uint32_t b4_off = (uint32_t)(((wn * 32 + (lane & 7)
                                         + ((lane >> 4) & 1) * 8) * LDT) * 2
                                       + ((lane >> 3) & 1) * 16);

    float acc[4][4][4];
#pragma unroll
    for (int i = 0; i < 4; i++)
#pragma unroll
        for (int j = 0; j < 4; j++)
#pragma unroll
            for (int e = 0; e < 4; e++) acc[i][j][e] = 0.f;

    const int nch = K / KC;

#define ISSUE(c) do {                                                       \
        const uint32_t st_ = sb + ((c) % 3) * STAGEB;                       \
        const size_t k0_ = (size_t)(c) * KC;                                \
        CP_ASYNC16(st_ + dA,                    pA + k0_);                  \
        CP_ASYNC16(st_ + dA + dstep,            pA + k0_ + rstep);          \
        CP_ASYNC16(st_ + ATILEB + dA,           pB + k0_);                  \
        CP_ASYNC16(st_ + ATILEB + dA + dstep,   pB + k0_ + rstep);          \
        CP_COMMIT();                                                        \
    } while (0)

    ISSUE(0);
    ISSUE(1);

    for (int c = 0; c < nch; c++) {
        if (c + 2 < nch) CP_WAIT1(); else CP_WAIT0();
        __syncthreads();
        if (c + 2 < nch) ISSUE(c + 2);

        const uint32_t tb = sb + (c % 3) * STAGEB;
        const uint32_t aT = tb;
        const uint32_t bT = tb + ATILEB;

#pragma unroll
        for (int ks = 0; ks < 2; ks++) {
            const uint32_t ksb = ks * 32;
            uint32_t af[4][4];
#pragma unroll
            for (int mt = 0; mt < 4; mt++)
                ldsm_x4(af[mt], aT + a_off + mt * (16 * LDT * 2) + ksb);
#pragma unroll
            for (int ntp = 0; ntp < 2; ntp++) {
                uint32_t bh[4];
                ldsm_x4(bh, bT + b4_off + ntp * (16 * LDT * 2) + ksb);
#pragma unroll
                for (int mt = 0; mt < 4; mt++) {
                    mma_f16(acc[mt][2 * ntp],     af[mt], bh[0], bh[1]);
                    mma_f16(acc[mt][2 * ntp + 1], af[mt], bh[2], bh[3]);
                }
            }
        }
    }
#undef ISSUE

#pragma unroll
    for (int mt = 0; mt < 4; mt++) {
        const int r = m0 + wm * 64 + mt * 16 + (lane >> 2);
#pragma unroll
        for (int nt = 0; nt < 4; nt++) {
            const int cc = n0 + wn * 32 + nt * 8 + (lane & 3) * 2;
            float2 v0 = {acc[mt][nt][0], acc[mt][nt][1]};
            float2 v1 = {acc[mt][nt][2], acc[mt][nt][3]};
            *(float2*)&C[(size_t)r * N + cc]       = v0;
            *(float2*)&C[(size_t)(r + 8) * N + cc] = v1;
        }
    }
}

// ---------------------------------------------------------------------------
// RMSNorm + RoPE (table-based), fp32 in (strided) -> single fp16
// ---------------------------------------------------------------------------
__global__ void __launch_bounds__(256)
rmsrope_h(const float* __restrict__ in, int rowstride,
          const float* __restrict__ w, int nheads,
          __half* __restrict__ out, const float2* __restrict__ cs)
{
    const int lane   = threadIdx.x & 31;
    const int warpid = threadIdx.x >> 5;
    const int row    = blockIdx.x * 8 + warpid;
    const int bt     = row / nheads;
    const int head   = row - bt * nheads;
    const int t      = bt & (T_ - 1);

    const float* p = in + (size_t)bt * rowstride + head * HD_;
    float2 x = *(const float2*)&p[2 * lane];

    float ss = x.x * x.x + x.y * x.y;
#pragma unroll
    for (int o = 16; o > 0; o >>= 1)
        ss += __shfl_xor_sync(0xffffffffu, ss, o);

    float rms = rsqrtf(ss * (1.0f / HD_) + 1e-6f);
    float xn1 = x.x * rms * w[2 * lane];
    float xn2 = x.y * rms * w[2 * lane + 1];

    float2 csv = cs[t * 32 + lane];
    float ox = xn1 * csv.x - xn2 * csv.y;
    float oy = xn2 * csv.x + xn1 * csv.y;

    const size_t idx = (size_t)bt * (nheads * HD_) + head * HD_ + 2 * lane;
    *(uint32_t*)&out[idx] = pack_h2(ox, oy);
}

// ---------------------------------------------------------------------------
// V convert + transpose: fp32 strided [bt, g*64] -> single fp16 [b,g,hd,T]
// ---------------------------------------------------------------------------
__global__ void __launch_bounds__(256)
vconv(const float* __restrict__ v, int rowstride, __half* __restrict__ vt)
{
    __shared__ float s[64][65];
    const int t0 = blockIdx.x * 64;
    const int g  = blockIdx.y;
    const int b  = blockIdx.z;
    const int tid = threadIdx.x;

#pragma unroll
    for (int it = 0; it < 4; it++) {
        int tr = it * 16 + (tid >> 4);
        int c4 = (tid & 15) * 4;
        float4 val = *(const float4*)&v[(size_t)(b * T_ + t0 + tr) * rowstride
                                        + g * HD_ + c4];
        s[tr][c4 + 0] = val.x; s[tr][c4 + 1] = val.y;
        s[tr][c4 + 2] = val.z; s[tr][c4 + 3] = val.w;
    }
    __syncthreads();

    const int hd  = tid >> 2;
    const int seg = tid & 3;
    __half hv[16];
#pragma unroll
    for (int j = 0; j < 16; j++)
        hv[j] = __float2half(s[seg * 16 + j][hd]);
    const size_t ob = ((size_t)(b * G_ + g) * HD_ + hd) * T_ + t0 + seg * 16;
    *(uint4*)&vt[ob]     = *(uint4*)&hv[0];
    *(uint4*)&vt[ob + 8] = *(uint4*)&hv[8];
}

// ---------------------------------------------------------------------------
// Causal GQA flash attention, HMMA fp16 single-pass.
// CTA = 128 q-rows, 4 warps (32 rows each), 64-key tiles,
// cp.async double-buffered K/V (one tile ahead), single sync per tile.
// ---------------------------------------------------------------------------
#define ASTR  72
#define ATILE (64 * ASTR * 2)            // 9216 B
#define AQT   (128 * ASTR * 2)           // 18432 B
#define KVSTG (2 * ATILE)                // 18432 B per stage (K, V)
#define ATT_SMEM (AQT + 2 * KVSTG)       // 55296 B
#define SC_LOG2E 0.18033688011112042f

__global__ void __launch_bounds__(128)
attn_mma(const __half* __restrict__ q16, const __half* __restrict__ k16,
         const __half* __restrict__ vt16, __half* __restrict__ o16)
{
    extern __shared__ char smraw[];
    const uint32_t sb  = smem_u32(smraw);
    const uint32_t sQ  = sb;
    const uint32_t sKV = sb + AQT;

    const int tid  = threadIdx.x;
    const int lane = tid & 31;
    const int w    = tid >> 5;
    const int mblk = gridDim.x - 1 - blockIdx.x;
    const int m0   = mblk * 128;
    const int h    = blockIdx.y;
    const int b    = blockIdx.z;
    const int g    = h >> 2;

    const __half* khb = k16 + ((size_t)b * T_ * G_ + g) * HD_;
    const __half* vhb = vt16 + (size_t)(b * G_ + g) * HD_ * T_;

    const int ntiles = (m0 + 128) / 64;

    const int ar = tid >> 3;             // 0..15
    const int ac = (tid & 7) * 8;
#define AISSUE(n0_, stg_) do {                                               \
        const uint32_t st_ = sKV + (uint32_t)(stg_) * KVSTG;                 \
        _Pragma("unroll")                                                    \
        for (int it_ = 0; it_ < 4; it_++) {                                  \
            const int rr_ = it_ * 16 + ar;                                   \
            const uint32_t so_ = (uint32_t)(rr_ * ASTR + ac) * 2;            \
            CP_ASYNC16(st_ + so_,         khb + (size_t)((n0_) + rr_) * (G_ * HD_) + ac); \
            CP_ASYNC16(st_ + ATILE + so_, vhb + (size_t)rr_ * T_ + (n0_) + ac); \
        }                                                                    \
        CP_COMMIT();                                                         \
    } while (0)

    AISSUE(0, 0);

    {
        const __half* qp = q16 + ((size_t)(b * T_ + m0) * H_ + h) * HD_;
        const uint32_t soff = (uint32_t)(ar * ASTR + ac) * 2;
#pragma unroll
        for (int it = 0; it < 8; it++) {
            uint4 a = *(const uint4*)(qp + (size_t)(it * 16 + ar) * (H_ * HD_) + ac);
            STS128(sQ + it * 16 * ASTR * 2 + soff, a);
        }
    }
    __syncthreads();

    uint32_t qf[2][4][4];
#pragma unroll
    for (int mt = 0; mt < 2; mt++) {
        const uint32_t a_off = (uint32_t)((w * 32 + mt * 16 + (lane & 15)) * ASTR * 2
                                          + (lane >> 4) * 16);
#pragma unroll
        for (int ks = 0; ks < 4; ks++)
            ldsm_x4(qf[mt][ks], sQ + a_off + ks * 32);
    }

    float o[2][8][4];
#pragma unroll
    for (int mt = 0; mt < 2; mt++)
#pragma unroll
        for (int nt = 0; nt < 8; nt++)
#pragma unroll
            for (int e = 0; e < 4; e++) o[mt][nt][e] = 0.f;
    float mrow[2][2] = {{-INFINITY, -INFINITY}, {-INFINITY, -INFINITY}};
    float lrow[2][2] = {{0.f, 0.f}, {0.f, 0.f}};

    const uint32_t b4_off = (uint32_t)((((lane & 7) + ((lane >> 4) & 1) * 8) * ASTR) * 2
                                       + ((lane >> 3) & 1) * 16);

    for (int t = 0; t < ntiles; t++) {
        CP_WAIT0();
        __syncthreads();
        if (t + 1 < ntiles) AISSUE((t + 1) * 64, (t + 1) & 1);

        const int n0 = t * 64;
        const uint32_t kvb = sKV + (uint32_t)(t & 1) * KVSTG;
        const uint32_t sK  = kvb;
        const uint32_t sV  = kvb + ATILE;

        const bool skip = (n0 > m0 + w * 32 + 31);
        if (!skip) {
            const bool needm = (n0 + 63 > m0 + w * 32);

            // ---- S = Q16 K16^T ----
            float s[2][8][4];
#pragma unroll
            for (int mt = 0; mt < 2; mt++)
#pragma unroll
                for (int nt = 0; nt < 8; nt++)
#pragma unroll
                    for (int e = 0; e < 4; e++) s[mt][nt][e] = 0.f;

#pragma unroll
            for (int ks = 0; ks < 4; ks++) {
#pragma unroll
                for (int ntp = 0; ntp < 4; ntp++) {
                    const uint32_t bo = b4_off + ntp * (16 * ASTR * 2) + ks * 32;
                    uint32_t bh[4];
                    ldsm_x4(bh, sK + bo);
#pragma unroll
                    for (int mt = 0; mt < 2; mt++) {
                        mma_f16(s[mt][2 * ntp],     qf[mt][ks], bh[0], bh[1]);
                        mma_f16(s[mt][2 * ntp + 1], qf[mt][ks], bh[2], bh[3]);
                    }
                }
            }

            // ---- per-group softmax; s dies into single-fp16 P fragments ----
            uint32_t ap[2][4][4];
#pragma unroll
            for (int mt = 0; mt < 2; mt++) {
                const int grow0 = m0 + w * 32 + mt * 16 + (lane >> 2);
                const int grow1 = grow0 + 8;
                float mx0 = -INFINITY, mx1 = -INFINITY;
#pragma unroll
                for (int nt = 0; nt < 8; nt++) {
                    const int col = n0 + nt * 8 + (lane & 3) * 2;
#pragma unroll
                    for (int e = 0; e < 2; e++) {
                        float v = s[mt][nt][e] * SC_LOG2E;
                        if (needm && (col + e > grow0)) v = -1e30f;
                        s[mt][nt][e] = v;
                        mx0 = fmaxf(mx0, v);
                    }
#pragma unroll
                    for (int e = 2; e < 4; e++) {
                        float v = s[mt][nt][e] * SC_LOG2E;
                        if (needm && (col + e - 2 > grow1)) v = -1e30f;
                        s[mt][nt][e] = v;
                        mx1 = fmaxf(mx1, v);
                    }
                }
                mx0 = fmaxf(mx0, __shfl_xor_sync(0xffffffffu, mx0, 1));
                mx0 = fmaxf(mx0, __shfl_xor_sync(0xffffffffu, mx0, 2));
                mx1 = fmaxf(mx1, __shfl_xor_sync(0xffffffffu, mx1, 1));
                mx1 = fmaxf(mx1, __shfl_xor_sync(0xffffffffu, mx1, 2));

                const float mn0 = fmaxf(mrow[mt][0], mx0);
                const float mn1 = fmaxf(mrow[mt][1], mx1);
                const float c0 = ex2(mrow[mt][0] - mn0);
                const float c1 = ex2(mrow[mt][1] - mn1);
                mrow[mt][0] = mn0; mrow[mt][1] = mn1;

                float s0 = 0.f, s1 = 0.f;
#pragma unroll
                for (int nt = 0; nt < 8; nt++) {
                    float p0 = ex2(s[mt][nt][0] - mn0);
                    float p1 = ex2(s[mt][nt][1] - mn0);
                    float p2 = ex2(s[mt][nt][2] - mn1);
                    float p3 = ex2(s[mt][nt][3] - mn1);
                    s[mt][nt][0] = p0; s[mt][nt][1] = p1;
                    s[mt][nt][2] = p2; s[mt][nt][3] = p3;
                    s0 += p0 + p1; s1 += p2 + p3;
                }
                s0 += __shfl_xor_sync(0xffffffffu, s0, 1);
                s0 += __shfl_xor_sync(0xffffffffu, s0, 2);
                s1 += __shfl_xor_sync(0xffffffffu, s1, 1);
                s1 += __shfl_xor_sync(0xffffffffu, s1, 2);
                lrow[mt][0] = lrow[mt][0] * c0 + s0;
                lrow[mt][1] = lrow[mt][1] * c1 + s1;

#pragma unroll
                for (int nt = 0; nt < 8; nt++) {
                    o[mt][nt][0] *= c0; o[mt][nt][1] *= c0;
                    o[mt][nt][2] *= c1; o[mt][nt][3] *= c1;
                }
#pragma unroll
                for (int ks = 0; ks < 4; ks++) {
                    ap[mt][ks][0] = pack_h2(s[mt][2 * ks][0],     s[mt][2 * ks][1]);
                    ap[mt][ks][1] = pack_h2(s[mt][2 * ks][2],     s[mt][2 * ks][3]);
                    ap[mt][ks][2] = pack_h2(s[mt][2 * ks + 1][0], s[mt][2 * ks + 1][1]);
                    ap[mt][ks][3] = pack_h2(s[mt][2 * ks + 1][2], s[mt][2 * ks + 1][3]);
                }
            }

            // ---- O += P16 V16 ----
#pragma unroll
            for (int ntp = 0; ntp < 4; ntp++) {
#pragma unroll
                for (int ks = 0; ks < 4; ks++) {
                    const uint32_t bo = b4_off + ntp * (16 * ASTR * 2) + ks * 32;
                    uint32_t vh[4];
                    ldsm_x4(vh, sV + bo);
#pragma unroll
                    for (int mt = 0; mt < 2; mt++) {
                        mma_f16(o[mt][2 * ntp],     ap[mt][ks], vh[0], vh[1]);
                        mma_f16(o[mt][2 * ntp + 1], ap[mt][ks], vh[2], vh[3]);
                    }
                }
            }
        }
    }
#undef AISSUE

    // ---- epilogue: normalize, emit single fp16 ----
#pragma unroll
    for (int mt = 0; mt < 2; mt++) {
        const float i0 = 1.f / lrow[mt][0];
        const float i1 = 1.f / lrow[mt][1];
        const int grow = m0 + w * 32 + mt * 16 + (lane >> 2);
        const size_t base0 = (size_t)(b * T_ + grow) * D_ + h * HD_ + (lane & 3) * 2;
        const size_t base1 = base0 + 8 * D_;
#pragma unroll
        for (int nt = 0; nt < 8; nt++) {
            *(uint32_t*)&o16[base0 + nt * 8] =
                pack_h2(o[mt][nt][0] * i0, o[mt][nt][1] * i0);
            *(uint32_t*)&o16[base1 + nt * 8] =
                pack_h2(o[mt][nt][2] * i1, o[mt][nt][3] * i1);
        }
    }
}

// ---------------------------------------------------------------------------
// Launch
// ---------------------------------------------------------------------------
extern "C" void kernel_launch(void* const* d_in, const int* in_sizes, int n_in,
                              void* d_out, int out_size)
{
    const float* x    = (const float*)d_in[0];
    const float* Wq   = (const float*)d_in[1];
    const float* Wk   = (const float*)d_in[2];
    const float* Wv   = (const float*)d_in[3];
    const float* Wo   = (const float*)d_in[4];
    const float* qn_w = (const float*)d_in[5];
    const float* kn_w = (const float*)d_in[6];
    float* out = (float*)d_out;

    float *qp, *kvp;
    float2* cs;
    __half *x16, *wq16, *wkv16, *wo16, *q16, *k16, *vt16, *o16;
    cudaGetSymbolAddress((void**)&qp, g_q);
    cudaGetSymbolAddress((void**)&kvp, g_kv);
    cudaGetSymbolAddress((void**)&cs, g_cs);
    cudaGetSymbolAddress((void**)&x16, g_x16);
    cudaGetSymbolAddress((void**)&wq16, g_wq16);
    cudaGetSymbolAddress((void**)&wkv16, g_wkv16);
    cudaGetSymbolAddress((void**)&wo16, g_wo16);
    cudaGetSymbolAddress((void**)&q16, g_q16);
    cudaGetSymbolAddress((void**)&k16, g_k16);
    cudaGetSymbolAddress((void**)&vt16, g_vt16);
    cudaGetSymbolAddress((void**)&o16, g_o16);

    cudaFuncSetAttribute(gemm_h1,
                         cudaFuncAttributeMaxDynamicSharedMemorySize, GEMM_SMEM);
    cudaFuncSetAttribute(attn_mma,
                         cudaFuncAttributeMaxDynamicSharedMemorySize, ATT_SMEM);

    // --- fused prologue ---
    prep<<<NB_TOT, 256>>>(x, Wq, Wk, Wv, Wo, x16, wq16, wkv16, wo16, cs);

    // --- projections: q and fused k|v ---
    gemm_h1<<<dim3(D_ / 128, BT_ / 128), 256, GEMM_SMEM>>>(
        x16, wq16, qp, BT_, D_, D_);
    gemm_h1<<<dim3(KVW / 128, BT_ / 128), 256, GEMM_SMEM>>>(
        x16, wkv16, kvp, BT_, KVW, D_);

    // --- RMSNorm + RoPE; V convert+transpose ---
    rmsrope_h<<<(BT_ * H_) / 8, 256>>>(qp, D_, qn_w, H_, q16, cs);
    rmsrope_h<<<(BT_ * G_) / 8, 256>>>(kvp, KVW, kn_w, G_, k16, cs);
    vconv<<<dim3(T_ / 64, G_, B_), 256>>>(kvp + 256, KVW, vt16);

    // --- causal GQA flash attention ---
    attn_mma<<<dim3(T_ / 128, H_, B_), 128, ATT_SMEM>>>(q16, k16, vt16, o16);

    // --- output projection ---
    gemm_h1<<<dim3(D_ / 128, BT_ / 128), 256, GEMM_SMEM>>>(
        o16, wo16, out, BT_, D_, D_);
}